// round 9
// baseline (speedup 1.0000x reference)
#include <cuda_runtime.h>
#include <cuda_bf16.h>
#include <cstdint>
#include <math.h>

// Problem constants
#define BB 32768
#define KK 8192
#define DD 384
#define JBLOCKS 256

constexpr float INV_T = 1.0f / 0.07f;

// Tiling: CTA tile 128x256, k-chunk 128; 8 warps as 2(M) x 4(N), warp tile 64x64
#define BM 128
#define BN 256
#define BKC 128
constexpr int A_UNITS = DD / 8;              // 48 16B-units per A row
constexpr int A_SEC_BYTES = BM * 16 * 16;    // 32768 per kc-section
constexpr int A_BYTES = 3 * A_SEC_BYTES;     // 98304 per stripe
constexpr int B_CHUNK = BN * BKC * 2;        // 65536 per chunk
constexpr int CTRL    = A_BYTES + 2 * B_CHUNK;  // 229376
constexpr int SMEM_TOTAL = CTRL + 128;          // 229504

// Work units: 2 n-tiles (512 cols) of one 128-row stripe = 6 chunks.
//   u < 4096 : GEMM1 (feat x cent): stripe=u>>4, seg=u&15
//   u >= 4096: GEMM2 (cent x cent): v=u-4096, stripe=v>>4, seg=v&15
// Output segments: oseg = seg*4 + wn  (64 disjoint column sets per row)
#define NTILES 2
#define NCHUNK 6
#define G1UNITS 4096
#define NUNITS  5120
#define OSEG    64

// Pre-swizzled GMEM images + outputs (device globals: no allocation allowed)
// A images are SECTION-MAJOR: unit index = sec*2048 + r*16 + ((u&15)^(r&7)),
// so each kc-section (32KB) is contiguous -> single cp.async.bulk.
__device__ uint4 g_featS[BB * DD * 2 / 16];
__device__ uint4 g_centA[KK * DD * 2 / 16];
__device__ uint4 g_centB[KK * DD * 2 / 16];
__device__ float g_rowmax[(size_t)OSEG * BB];
__device__ int   g_rowarg[(size_t)OSEG * BB];
__device__ float g_centpart[(size_t)OSEG * KK];
__device__ float g_jpart[JBLOCKS];
__device__ unsigned g_work;

// ---------------------------------------------------------------------------
__device__ __forceinline__ uint32_t smem_u32(const void* p) {
    return (uint32_t)__cvta_generic_to_shared(p);
}
__device__ __forceinline__ void mbar_init(uint32_t a, uint32_t c) {
    asm volatile("mbarrier.init.shared.b64 [%0], %1;" :: "r"(a), "r"(c) : "memory");
}
__device__ __forceinline__ void mbar_expect(uint32_t a, uint32_t bytes) {
    asm volatile("mbarrier.arrive.expect_tx.shared.b64 _, [%0], %1;"
                 :: "r"(a), "r"(bytes) : "memory");
}
__device__ __forceinline__ void bulk_g2s(uint32_t dst, const void* src,
                                         uint32_t bytes, uint32_t mb) {
    asm volatile(
        "cp.async.bulk.shared::cluster.global.mbarrier::complete_tx::bytes "
        "[%0], [%1], %2, [%3];"
        :: "r"(dst), "l"(src), "r"(bytes), "r"(mb) : "memory");
}
__device__ __forceinline__ void mbar_wait(uint32_t addr, uint32_t parity) {
    asm volatile(
        "{\n\t.reg .pred P;\n\t"
        "WL%=:\n\t"
        "mbarrier.try_wait.parity.acquire.cta.shared::cta.b64 P, [%0], %1, 0x989680;\n\t"
        "@P bra WD%=;\n\t"
        "bra WL%=;\n\t"
        "WD%=:\n\t}"
        :: "r"(addr), "r"(parity) : "memory");
}
__device__ __forceinline__ uint32_t atom_inc_acqrel(uint32_t addr) {
    uint32_t old;
    asm volatile("atom.add.acq_rel.cta.shared::cta.u32 %0, [%1], 1;"
                 : "=r"(old) : "r"(addr) : "memory");
    return old;
}
#define FENCE_ASYNC() asm volatile("fence.proxy.async.shared::cta;" ::: "memory")

__device__ __forceinline__ void ldsm4(uint32_t (&d)[4], uint32_t addr) {
    asm volatile("ldmatrix.sync.aligned.m8n8.x4.shared.b16 {%0,%1,%2,%3}, [%4];"
                 : "=r"(d[0]), "=r"(d[1]), "=r"(d[2]), "=r"(d[3]) : "r"(addr));
}

// ---------------------------------------------------------------------------
// Prep: features fp32 -> bf16 section-major pre-swizzled stripes. Resets g_work.
// ---------------------------------------------------------------------------
__global__ void k_prep_feat(const float* __restrict__ feat) {
    if (blockIdx.x == 0 && threadIdx.x == 0) g_work = 0u;
    const int NU = BB * A_UNITS;
    for (int idx = blockIdx.x * blockDim.x + threadIdx.x; idx < NU;
         idx += gridDim.x * blockDim.x) {
        int u = idx % A_UNITS;
        int r = (idx / A_UNITS) % BM;
        int s = idx / (A_UNITS * BM);
        const float4* src =
            (const float4*)(feat + (size_t)(s * BM + r) * DD + u * 8);
        float4 f0 = src[0], f1 = src[1];
        __nv_bfloat162 p0 = __floats2bfloat162_rn(f0.x, f0.y);
        __nv_bfloat162 p1 = __floats2bfloat162_rn(f0.z, f0.w);
        __nv_bfloat162 p2 = __floats2bfloat162_rn(f1.x, f1.y);
        __nv_bfloat162 p3 = __floats2bfloat162_rn(f1.z, f1.w);
        uint4 v;
        v.x = *(uint32_t*)&p0; v.y = *(uint32_t*)&p1;
        v.z = *(uint32_t*)&p2; v.w = *(uint32_t*)&p3;
        g_featS[s * (BM * A_UNITS) + (u >> 4) * (BM * 16)
                + r * 16 + ((u & 15) ^ (r & 7))] = v;
    }
}

// ---------------------------------------------------------------------------
// Prep: centroids normalize -> bf16 as section-major A stripes + B chunks.
// ---------------------------------------------------------------------------
__global__ void k_prep_cent(const float* __restrict__ cent) {
    __shared__ float red[4];
    int row = blockIdx.x, t = threadIdx.x;
    const float* src = cent + (size_t)row * DD;
    float v0 = src[t], v1 = src[t + 128], v2 = src[t + 256];
    float s = v0 * v0 + v1 * v1 + v2 * v2;
#pragma unroll
    for (int o = 16; o > 0; o >>= 1) s += __shfl_xor_sync(0xffffffffu, s, o);
    if ((t & 31) == 0) red[t >> 5] = s;
    __syncthreads();
    float inv = 1.0f / fmaxf(sqrtf(red[0] + red[1] + red[2] + red[3]), 1e-12f);

    int j = -1;
    if (t < 48) j = t;
    else if (t >= 64 && t < 112) j = t - 64;
    if (j >= 0) {
        const float4* sp = (const float4*)(src + j * 8);
        float4 f0 = sp[0], f1 = sp[1];
        __nv_bfloat162 p0 = __floats2bfloat162_rn(f0.x * inv, f0.y * inv);
        __nv_bfloat162 p1 = __floats2bfloat162_rn(f0.z * inv, f0.w * inv);
        __nv_bfloat162 p2 = __floats2bfloat162_rn(f1.x * inv, f1.y * inv);
        __nv_bfloat162 p3 = __floats2bfloat162_rn(f1.z * inv, f1.w * inv);
        uint4 v;
        v.x = *(uint32_t*)&p0; v.y = *(uint32_t*)&p1;
        v.z = *(uint32_t*)&p2; v.w = *(uint32_t*)&p3;
        if (t < 48) {
            int sA = row >> 7, r = row & 127;
            g_centA[sA * (BM * A_UNITS) + (j >> 4) * (BM * 16)
                    + r * 16 + ((j & 15) ^ (r & 7))] = v;
        } else {
            int nt = row >> 8, rr = row & 255, kc = j >> 4, uu = j & 15;
            g_centB[(size_t)(nt * 3 + kc) * 4096 + rr * 16 + (uu ^ (rr & 7))] = v;
        }
    }
}

// ---------------------------------------------------------------------------
// Persistent fused GEMM: 152 CTAs, dynamic unit counter, pipeline never
// drains. A is split into 3 kc-sections with individual mbars; section kc's
// next-unit refill is issued by the last finisher of chunk 3+kc (its final
// reader), 3 chunks before first use -> no unit-start A bubble.
// B slots fill 3x per unit (odd) -> wait parity is (k + (c>>1)) & 1.
// ---------------------------------------------------------------------------
__global__ void __launch_bounds__(256, 1) gemm_all() {
    extern __shared__ char smem[];
    const int tid = threadIdx.x, lane = tid & 31, wid = tid >> 5;
    const int wm = wid >> 2, wn = wid & 3;
    const uint32_t sb = smem_u32(smem);
    const uint32_t mbA = sb + CTRL;          // A section mbars[3]
    const uint32_t mbF = sb + CTRL + 24;     // B full mbars[2]
    const uint32_t cnt = sb + CTRL + 40;     // 6 monotonic u32 counters
    volatile uint32_t* const u_slot = (volatile uint32_t*)(smem + CTRL + 64);

    auto issueA = [&](unsigned uu, int sec) {
        int isG1 = uu < G1UNITS;
        int stripe = (int)(isG1 ? uu : uu - G1UNITS) >> 4;
        const uint4* src = (isG1 ? g_featS : g_centA)
                         + (size_t)stripe * (BM * A_UNITS) + sec * (BM * 16);
        mbar_expect(mbA + sec * 8, A_SEC_BYTES);
        bulk_g2s(sb + sec * A_SEC_BYTES, src, A_SEC_BYTES, mbA + sec * 8);
    };
    auto issueB = [&](unsigned uu, int c) {
        int seg = (int)((uu < G1UNITS ? uu : uu - G1UNITS) & 15u);
        const uint4* src =
            g_centB + (size_t)((seg * NTILES + c / 3) * 3 + c % 3) * 4096;
        int slot = c & 1;
        mbar_expect(mbF + slot * 8, B_CHUNK);
        bulk_g2s(sb + A_BYTES + slot * B_CHUNK, src, B_CHUNK, mbF + slot * 8);
    };

    if (tid == 0) {
        mbar_init(mbA, 1); mbar_init(mbA + 8, 1); mbar_init(mbA + 16, 1);
        mbar_init(mbF, 1); mbar_init(mbF + 8, 1);
        *u_slot = atomicAdd(&g_work, 1u);
    }
    if (tid < NCHUNK) *(uint32_t*)(smem + CTRL + 40 + tid * 4) = 0u;
    __syncthreads();

    unsigned u = *u_slot;
    int k = 0;
    if (tid == 0 && u < NUNITS) {
        issueA(u, 0); issueA(u, 1); issueA(u, 2);
        issueB(u, 0); issueB(u, 1);
    }

    while (u < NUNITS) {
        const int isG1 = u < G1UNITS;
        const int v_ = isG1 ? (int)u : (int)u - G1UNITS;
        const int stripe = v_ >> 4, seg = v_ & 15;
        const int row0 = stripe * BM;
        const int col_begin = seg * (NTILES * BN);

        float acc[4][8][4];
        float bestv[8];
        int   besti[8];
        float rsum[8];
#pragma unroll
        for (int s = 0; s < 8; ++s) {
            bestv[s] = __int_as_float(0xff800000);
            besti[s] = 0x7fffffff;
            rsum[s]  = 0.0f;
        }

        for (int c = 0; c < NCHUNK; ++c) {
            const int slot = c & 1, kc = c % 3, nt = c / 3;
            if (c < 3) mbar_wait(mbA + c * 8, (uint32_t)(k & 1));
            mbar_wait(mbF + slot * 8, (uint32_t)((k + (c >> 1)) & 1));
            const uint32_t bbase = sb + A_BYTES + slot * B_CHUNK;
            const uint32_t abase = sb + kc * A_SEC_BYTES;

            if (kc == 0) {
#pragma unroll
                for (int mf = 0; mf < 4; ++mf)
#pragma unroll
                    for (int nf = 0; nf < 8; ++nf)
#pragma unroll
                        for (int q = 0; q < 4; ++q) acc[mf][nf][q] = 0.0f;
            }

#pragma unroll
            for (int ks = 0; ks < 8; ++ks) {
                uint32_t a[4][4], b[4][4];
#pragma unroll
                for (int mf = 0; mf < 4; ++mf) {
                    int r = wm * 64 + mf * 16 + (lane & 15);
                    int ul = ks * 2 + (lane >> 4);
                    ldsm4(a[mf],
                          abase + (uint32_t)(r * 16 + (ul ^ (r & 7))) * 16u);
                }
#pragma unroll
                for (int np = 0; np < 4; ++np) {
                    int r = wn * 64 + np * 16 + (lane & 7) + ((lane >> 4) << 3);
                    int uu = ks * 2 + ((lane >> 3) & 1);
                    ldsm4(b[np],
                          bbase + (uint32_t)(r * 16 + (uu ^ (r & 7))) * 16u);
                }
#pragma unroll
                for (int mf = 0; mf < 4; ++mf)
#pragma unroll
                    for (int nf = 0; nf < 8; ++nf) {
                        int np = nf >> 1, h = nf & 1;
                        asm volatile(
                            "mma.sync.aligned.m16n8k16.row.col.f32.bf16.bf16.f32 "
                            "{%0,%1,%2,%3}, {%4,%5,%6,%7}, {%8,%9}, {%0,%1,%2,%3};\n"
                            : "+f"(acc[mf][nf][0]), "+f"(acc[mf][nf][1]),
                              "+f"(acc[mf][nf][2]), "+f"(acc[mf][nf][3])
                            : "r"(a[mf][0]), "r"(a[mf][1]), "r"(a[mf][2]),
                              "r"(a[mf][3]),
                              "r"(b[np][h * 2]), "r"(b[np][h * 2 + 1]));
                    }
            }

            // Buffer release + refill/prefetch by the LAST finisher of chunk c.
            if (lane == 0) {
                uint32_t old = atom_inc_acqrel(cnt + c * 4);
                if (old == (uint32_t)(8 * k + 7)) {
                    FENCE_ASYNC();
                    if (c <= 3) issueB(u, c + 2);
                    if (c == 2) {
                        *u_slot = atomicAdd(&g_work, 1u);   // grab next unit
                    } else if (c == 3) {
                        unsigned un = *u_slot;
                        if (un < NUNITS) issueA(un, 0);
                    } else if (c == 4) {
                        unsigned un = *u_slot;
                        if (un < NUNITS) { issueA(un, 1); issueB(un, 0); }
                    } else if (c == 5) {
                        unsigned un = *u_slot;
                        if (un < NUNITS) { issueA(un, 2); issueB(un, 1); }
                    }
                }
            }

            if (kc == 2) {
                int cbase = col_begin + nt * BN + wn * 64 + 2 * (lane & 3);
#pragma unroll
                for (int mf = 0; mf < 4; ++mf)
#pragma unroll
                    for (int nf = 0; nf < 8; ++nf) {
                        int col = cbase + nf * 8;
                        int s0 = mf * 2, s1 = mf * 2 + 1;
                        if (isG1) {
                            float v0 = acc[mf][nf][0], v1 = acc[mf][nf][1];
                            float v2 = acc[mf][nf][2], v3 = acc[mf][nf][3];
                            if (v0 > bestv[s0]) { bestv[s0] = v0; besti[s0] = col; }
                            if (v1 > bestv[s0]) { bestv[s0] = v1; besti[s0] = col + 1; }
                            if (v2 > bestv[s1]) { bestv[s1] = v2; besti[s1] = col; }
                            if (v3 > bestv[s1]) { bestv[s1] = v3; besti[s1] = col + 1; }
                        } else {
                            rsum[s0] += __expf(acc[mf][nf][0] * INV_T)
                                      + __expf(acc[mf][nf][1] * INV_T);
                            rsum[s1] += __expf(acc[mf][nf][2] * INV_T)
                                      + __expf(acc[mf][nf][3] * INV_T);
                        }
                    }
            }
        }

        // Direct-to-global writeback (overlaps next unit's prefetch fills).
        const int oseg = seg * 4 + wn;
#pragma unroll
        for (int s = 0; s < 8; ++s) {
            int row = wm * 64 + (s >> 1) * 16 + (lane >> 2) + (s & 1) * 8;
            if (isG1) {
                float vv = bestv[s];
                int ii = besti[s];
#pragma unroll
                for (int o = 1; o <= 2; o <<= 1) {
                    float ov = __shfl_xor_sync(0xffffffffu, vv, o);
                    int oi = __shfl_xor_sync(0xffffffffu, ii, o);
                    if (ov > vv || (ov == vv && oi < ii)) { vv = ov; ii = oi; }
                }
                if ((lane & 3) == 0) {
                    g_rowmax[(size_t)oseg * BB + row0 + row] = vv;
                    g_rowarg[(size_t)oseg * BB + row0 + row] = ii;
                }
            } else {
                float vv = rsum[s];
                vv += __shfl_xor_sync(0xffffffffu, vv, 1);
                vv += __shfl_xor_sync(0xffffffffu, vv, 2);
                if ((lane & 3) == 0)
                    g_centpart[(size_t)oseg * KK + row0 + row] = vv;
            }
        }

        __syncthreads();   // broadcast u_slot; all warps aligned to next unit
        ++k;
        u = *u_slot;
    }
}

// ---------------------------------------------------------------------------
// Per-sample loss: merge 64 disjoint-segment candidates per row (first-max
// semantics via (>, ==&&idx<)), add 64 centroid partial sums, reduce.
// ---------------------------------------------------------------------------
__global__ void k_finalj() {
    __shared__ float red[4];
    int i = blockIdx.x * 128 + threadIdx.x;
    float m = __int_as_float(0xff800000);
    int a = 0x7fffffff;
#pragma unroll 8
    for (int o = 0; o < OSEG; ++o) {
        float ms = g_rowmax[(size_t)o * BB + i];
        int as_ = g_rowarg[(size_t)o * BB + i];
        if (ms > m || (ms == m && as_ < a)) { m = ms; a = as_; }
    }
    float S = 0.0f;
#pragma unroll 8
    for (int o = 0; o < OSEG; ++o) S += g_centpart[(size_t)o * KK + a];
    float mt = m * INV_T;
    float J = mt - logf(expf(mt) + S);
    float s = J;
#pragma unroll
    for (int o = 16; o > 0; o >>= 1) s += __shfl_xor_sync(0xffffffffu, s, o);
    if ((threadIdx.x & 31) == 0) red[threadIdx.x >> 5] = s;
    __syncthreads();
    if (threadIdx.x == 0) g_jpart[blockIdx.x] = red[0] + red[1] + red[2] + red[3];
}

__global__ void k_reduce(float* out) {
    __shared__ float red[8];
    int t = threadIdx.x; // 256
    float s = g_jpart[t];
#pragma unroll
    for (int o = 16; o > 0; o >>= 1) s += __shfl_xor_sync(0xffffffffu, s, o);
    if ((t & 31) == 0) red[t >> 5] = s;
    __syncthreads();
    if (t == 0) {
        float tot = 0.0f;
        for (int i = 0; i < 8; ++i) tot += red[i];
        out[0] = -tot / (float)BB;
    }
}

// ---------------------------------------------------------------------------
extern "C" void kernel_launch(void* const* d_in, const int* in_sizes, int n_in,
                              void* d_out, int out_size) {
    const float* feat = (const float*)d_in[0];
    const float* cent = (const float*)d_in[1];
    if (n_in >= 2 && in_sizes[0] == KK * DD && in_sizes[1] == BB * DD) {
        feat = (const float*)d_in[1];
        cent = (const float*)d_in[0];
    }

    cudaFuncSetAttribute((const void*)gemm_all,
                         cudaFuncAttributeMaxDynamicSharedMemorySize, SMEM_TOTAL);

    k_prep_feat<<<3072, 256>>>(feat);
    k_prep_cent<<<KK, 128>>>(cent);
    gemm_all<<<152, 256, SMEM_TOTAL>>>();
    k_finalj<<<JBLOCKS, 128>>>();
    k_reduce<<<1, 256>>>((float*)d_out);
}

// round 12
// speedup vs baseline: 1.0573x; 1.0573x over previous
#include <cuda_runtime.h>
#include <cuda_bf16.h>
#include <cstdint>
#include <math.h>

// Problem constants
#define BB 32768
#define KK 8192
#define DD 384
#define JBLOCKS 256

constexpr float INV_T = 1.0f / 0.07f;

// Tiling: CTA tile 128x256, k-chunk 128; 8 warps as 2(M) x 4(N), warp tile 64x64
#define BM 128
#define BN 256
#define BKC 128
constexpr int A_UNITS = DD / 8;              // 48 16B-units per A row
constexpr int A_SEC_BYTES = BM * 16 * 16;    // 32768 per kc-section
constexpr int A_BYTES = 3 * A_SEC_BYTES;     // 98304 per stripe
constexpr int B_CHUNK = BN * BKC * 2;        // 65536 per chunk
constexpr int CTRL    = A_BYTES + 2 * B_CHUNK;  // 229376
constexpr int SMEM_TOTAL = CTRL + 128;          // 229504

// Work units: 4 n-tiles (1024 cols) of one 128-row stripe = 12 chunks.
//   u < 2048 : GEMM1 (feat x cent): stripe=u>>3, seg=u&7
//   u >= 2048: GEMM2 (cent x cent): v=u-2048, stripe=v>>3, seg=v&7
// Output segments: oseg = seg*4 + wn  (32 disjoint column sets per row)
#define NTILES 4
#define NCHUNK 12
#define G1UNITS 2048
#define NUNITS  2560
#define OSEG    32

// Pre-swizzled GMEM images + outputs (device globals: no allocation allowed)
// A images are SECTION-MAJOR: unit index = sec*2048 + r*16 + ((u&15)^(r&7)),
// so each kc-section (32KB) is contiguous -> single cp.async.bulk.
__device__ uint4 g_featS[BB * DD * 2 / 16];
__device__ uint4 g_centA[KK * DD * 2 / 16];
__device__ uint4 g_centB[KK * DD * 2 / 16];
__device__ float g_rowmax[(size_t)OSEG * BB];
__device__ int   g_rowarg[(size_t)OSEG * BB];
__device__ float g_centpart[(size_t)OSEG * KK];
__device__ float g_jpart[JBLOCKS];
__device__ unsigned g_work;

// ---------------------------------------------------------------------------
__device__ __forceinline__ uint32_t smem_u32(const void* p) {
    return (uint32_t)__cvta_generic_to_shared(p);
}
__device__ __forceinline__ void mbar_init(uint32_t a, uint32_t c) {
    asm volatile("mbarrier.init.shared.b64 [%0], %1;" :: "r"(a), "r"(c) : "memory");
}
__device__ __forceinline__ void mbar_expect(uint32_t a, uint32_t bytes) {
    asm volatile("mbarrier.arrive.expect_tx.shared.b64 _, [%0], %1;"
                 :: "r"(a), "r"(bytes) : "memory");
}
__device__ __forceinline__ void bulk_g2s(uint32_t dst, const void* src,
                                         uint32_t bytes, uint32_t mb) {
    asm volatile(
        "cp.async.bulk.shared::cluster.global.mbarrier::complete_tx::bytes "
        "[%0], [%1], %2, [%3];"
        :: "r"(dst), "l"(src), "r"(bytes), "r"(mb) : "memory");
}
__device__ __forceinline__ void mbar_wait(uint32_t addr, uint32_t parity) {
    asm volatile(
        "{\n\t.reg .pred P;\n\t"
        "WL%=:\n\t"
        "mbarrier.try_wait.parity.acquire.cta.shared::cta.b64 P, [%0], %1, 0x989680;\n\t"
        "@P bra WD%=;\n\t"
        "bra WL%=;\n\t"
        "WD%=:\n\t}"
        :: "r"(addr), "r"(parity) : "memory");
}
__device__ __forceinline__ uint32_t atom_inc_acqrel(uint32_t addr) {
    uint32_t old;
    asm volatile("atom.add.acq_rel.cta.shared::cta.u32 %0, [%1], 1;"
                 : "=r"(old) : "r"(addr) : "memory");
    return old;
}
#define FENCE_ASYNC() asm volatile("fence.proxy.async.shared::cta;" ::: "memory")

__device__ __forceinline__ void ldsm4(uint32_t (&d)[4], uint32_t addr) {
    asm volatile("ldmatrix.sync.aligned.m8n8.x4.shared.b16 {%0,%1,%2,%3}, [%4];"
                 : "=r"(d[0]), "=r"(d[1]), "=r"(d[2]), "=r"(d[3]) : "r"(addr));
}

// ---------------------------------------------------------------------------
// Prep: features fp32 -> bf16 section-major pre-swizzled stripes. Resets g_work.
// ---------------------------------------------------------------------------
__global__ void k_prep_feat(const float* __restrict__ feat) {
    if (blockIdx.x == 0 && threadIdx.x == 0) g_work = 0u;
    const int NU = BB * A_UNITS;
    for (int idx = blockIdx.x * blockDim.x + threadIdx.x; idx < NU;
         idx += gridDim.x * blockDim.x) {
        int u = idx % A_UNITS;
        int r = (idx / A_UNITS) % BM;
        int s = idx / (A_UNITS * BM);
        const float4* src =
            (const float4*)(feat + (size_t)(s * BM + r) * DD + u * 8);
        float4 f0 = src[0], f1 = src[1];
        __nv_bfloat162 p0 = __floats2bfloat162_rn(f0.x, f0.y);
        __nv_bfloat162 p1 = __floats2bfloat162_rn(f0.z, f0.w);
        __nv_bfloat162 p2 = __floats2bfloat162_rn(f1.x, f1.y);
        __nv_bfloat162 p3 = __floats2bfloat162_rn(f1.z, f1.w);
        uint4 v;
        v.x = *(uint32_t*)&p0; v.y = *(uint32_t*)&p1;
        v.z = *(uint32_t*)&p2; v.w = *(uint32_t*)&p3;
        g_featS[s * (BM * A_UNITS) + (u >> 4) * (BM * 16)
                + r * 16 + ((u & 15) ^ (r & 7))] = v;
    }
}

// ---------------------------------------------------------------------------
// Prep: centroids normalize -> bf16 as section-major A stripes + B chunks.
// ---------------------------------------------------------------------------
__global__ void k_prep_cent(const float* __restrict__ cent) {
    __shared__ float red[4];
    int row = blockIdx.x, t = threadIdx.x;
    const float* src = cent + (size_t)row * DD;
    float v0 = src[t], v1 = src[t + 128], v2 = src[t + 256];
    float s = v0 * v0 + v1 * v1 + v2 * v2;
#pragma unroll
    for (int o = 16; o > 0; o >>= 1) s += __shfl_xor_sync(0xffffffffu, s, o);
    if ((t & 31) == 0) red[t >> 5] = s;
    __syncthreads();
    float inv = 1.0f / fmaxf(sqrtf(red[0] + red[1] + red[2] + red[3]), 1e-12f);

    int j = -1;
    if (t < 48) j = t;
    else if (t >= 64 && t < 112) j = t - 64;
    if (j >= 0) {
        const float4* sp = (const float4*)(src + j * 8);
        float4 f0 = sp[0], f1 = sp[1];
        __nv_bfloat162 p0 = __floats2bfloat162_rn(f0.x * inv, f0.y * inv);
        __nv_bfloat162 p1 = __floats2bfloat162_rn(f0.z * inv, f0.w * inv);
        __nv_bfloat162 p2 = __floats2bfloat162_rn(f1.x * inv, f1.y * inv);
        __nv_bfloat162 p3 = __floats2bfloat162_rn(f1.z * inv, f1.w * inv);
        uint4 v;
        v.x = *(uint32_t*)&p0; v.y = *(uint32_t*)&p1;
        v.z = *(uint32_t*)&p2; v.w = *(uint32_t*)&p3;
        if (t < 48) {
            int sA = row >> 7, r = row & 127;
            g_centA[sA * (BM * A_UNITS) + (j >> 4) * (BM * 16)
                    + r * 16 + ((j & 15) ^ (r & 7))] = v;
        } else {
            int nt = row >> 8, rr = row & 255, kc = j >> 4, uu = j & 15;
            g_centB[(size_t)(nt * 3 + kc) * 4096 + rr * 16 + (uu ^ (rr & 7))] = v;
        }
    }
}

// ---------------------------------------------------------------------------
// Persistent fused GEMM: 152 CTAs, dynamic unit counter, pipeline never
// drains. 12-chunk units (round-7 granularity). A split into 3 kc-sections
// with individual mbars; section kc's next-unit refill issues at the last
// finisher of chunk 9+kc (its final reader), 3 chunks before first use ->
// no unit-start A bubble. B slots fill 6x per unit (even) -> parity (c>>1)&1.
// ---------------------------------------------------------------------------
__global__ void __launch_bounds__(256, 1) gemm_all() {
    extern __shared__ char smem[];
    const int tid = threadIdx.x, lane = tid & 31, wid = tid >> 5;
    const int wm = wid >> 2, wn = wid & 3;
    const uint32_t sb = smem_u32(smem);
    const uint32_t mbA = sb + CTRL;          // A section mbars[3]
    const uint32_t mbF = sb + CTRL + 24;     // B full mbars[2]
    const uint32_t cnt = sb + CTRL + 40;     // 12 monotonic u32 counters
    uint32_t* const u_slot = (uint32_t*)(smem + CTRL + 88);

    auto issueA = [&](unsigned uu, int sec) {
        int isG1 = uu < G1UNITS;
        int stripe = (int)(isG1 ? uu : uu - G1UNITS) >> 3;
        const uint4* src = (isG1 ? g_featS : g_centA)
                         + (size_t)stripe * (BM * A_UNITS) + sec * (BM * 16);
        mbar_expect(mbA + sec * 8, A_SEC_BYTES);
        bulk_g2s(sb + sec * A_SEC_BYTES, src, A_SEC_BYTES, mbA + sec * 8);
    };
    auto issueB = [&](unsigned uu, int c) {
        int seg = (int)((uu < G1UNITS ? uu : uu - G1UNITS) & 7u);
        const uint4* src =
            g_centB + (size_t)((seg * NTILES + c / 3) * 3 + c % 3) * 4096;
        int slot = c & 1;
        mbar_expect(mbF + slot * 8, B_CHUNK);
        bulk_g2s(sb + A_BYTES + slot * B_CHUNK, src, B_CHUNK, mbF + slot * 8);
    };

    if (tid == 0) {
        mbar_init(mbA, 1); mbar_init(mbA + 8, 1); mbar_init(mbA + 16, 1);
        mbar_init(mbF, 1); mbar_init(mbF + 8, 1);
        *u_slot = atomicAdd(&g_work, 1u);
    }
    if (tid < NCHUNK) *(uint32_t*)(smem + CTRL + 40 + tid * 4) = 0u;
    __syncthreads();

    unsigned u = *u_slot;
    int k = 0;
    if (tid == 0 && u < NUNITS) {
        issueA(u, 0); issueA(u, 1); issueA(u, 2);
        issueB(u, 0); issueB(u, 1);
    }

    while (u < NUNITS) {
        const int isG1 = u < G1UNITS;
        const int v_ = isG1 ? (int)u : (int)u - G1UNITS;
        const int stripe = v_ >> 3, seg = v_ & 7;
        const int row0 = stripe * BM;
        const int col_begin = seg * (NTILES * BN);

        float acc[4][8][4];
        float bestv[8];
        int   besti[8];
        float rsum[8];
#pragma unroll
        for (int s = 0; s < 8; ++s) {
            bestv[s] = __int_as_float(0xff800000);
            besti[s] = 0x7fffffff;
            rsum[s]  = 0.0f;
        }

        for (int c = 0; c < NCHUNK; ++c) {
            const int slot = c & 1, kc = c % 3, nt = c / 3;
            if (c < 3) mbar_wait(mbA + c * 8, (uint32_t)(k & 1));
            mbar_wait(mbF + slot * 8, (uint32_t)((c >> 1) & 1));
            const uint32_t bbase = sb + A_BYTES + slot * B_CHUNK;
            const uint32_t abase = sb + kc * A_SEC_BYTES;

            if (kc == 0) {
#pragma unroll
                for (int mf = 0; mf < 4; ++mf)
#pragma unroll
                    for (int nf = 0; nf < 8; ++nf)
#pragma unroll
                        for (int q = 0; q < 4; ++q) acc[mf][nf][q] = 0.0f;
            }

#pragma unroll
            for (int ks = 0; ks < 8; ++ks) {
                uint32_t a[4][4], b[4][4];
#pragma unroll
                for (int mf = 0; mf < 4; ++mf) {
                    int r = wm * 64 + mf * 16 + (lane & 15);
                    int ul = ks * 2 + (lane >> 4);
                    ldsm4(a[mf],
                          abase + (uint32_t)(r * 16 + (ul ^ (r & 7))) * 16u);
                }
#pragma unroll
                for (int np = 0; np < 4; ++np) {
                    int r = wn * 64 + np * 16 + (lane & 7) + ((lane >> 4) << 3);
                    int uu = ks * 2 + ((lane >> 3) & 1);
                    ldsm4(b[np],
                          bbase + (uint32_t)(r * 16 + (uu ^ (r & 7))) * 16u);
                }
#pragma unroll
                for (int mf = 0; mf < 4; ++mf)
#pragma unroll
                    for (int nf = 0; nf < 8; ++nf) {
                        int np = nf >> 1, h = nf & 1;
                        asm volatile(
                            "mma.sync.aligned.m16n8k16.row.col.f32.bf16.bf16.f32 "
                            "{%0,%1,%2,%3}, {%4,%5,%6,%7}, {%8,%9}, {%0,%1,%2,%3};\n"
                            : "+f"(acc[mf][nf][0]), "+f"(acc[mf][nf][1]),
                              "+f"(acc[mf][nf][2]), "+f"(acc[mf][nf][3])
                            : "r"(a[mf][0]), "r"(a[mf][1]), "r"(a[mf][2]),
                              "r"(a[mf][3]),
                              "r"(b[np][h * 2]), "r"(b[np][h * 2 + 1]));
                    }
            }

            // Buffer release + refill/prefetch by the LAST finisher of chunk c.
            // u_slot visibility: stored before the writer's cnt[c+1] release;
            // read only by later chunks' last finishers (acquire chain).
            if (lane == 0) {
                uint32_t old = atom_inc_acqrel(cnt + c * 4);
                if (old == (uint32_t)(8 * k + 7)) {
                    FENCE_ASYNC();
                    if (c <= NCHUNK - 3) issueB(u, c + 2);
                    if (c == 8) {
                        *u_slot = atomicAdd(&g_work, 1u);   // grab next unit
                    } else if (c == 9) {
                        unsigned un = *u_slot;
                        if (un < NUNITS) issueA(un, 0);
                    } else if (c == 10) {
                        unsigned un = *u_slot;
                        if (un < NUNITS) { issueA(un, 1); issueB(un, 0); }
                    } else if (c == 11) {
                        unsigned un = *u_slot;
                        if (un < NUNITS) { issueA(un, 2); issueB(un, 1); }
                    }
                }
            }

            if (kc == 2) {
                int cbase = col_begin + nt * BN + wn * 64 + 2 * (lane & 3);
#pragma unroll
                for (int mf = 0; mf < 4; ++mf)
#pragma unroll
                    for (int nf = 0; nf < 8; ++nf) {
                        int col = cbase + nf * 8;
                        int s0 = mf * 2, s1 = mf * 2 + 1;
                        if (isG1) {
                            float v0 = acc[mf][nf][0], v1 = acc[mf][nf][1];
                            float v2 = acc[mf][nf][2], v3 = acc[mf][nf][3];
                            if (v0 > bestv[s0]) { bestv[s0] = v0; besti[s0] = col; }
                            if (v1 > bestv[s0]) { bestv[s0] = v1; besti[s0] = col + 1; }
                            if (v2 > bestv[s1]) { bestv[s1] = v2; besti[s1] = col; }
                            if (v3 > bestv[s1]) { bestv[s1] = v3; besti[s1] = col + 1; }
                        } else {
                            rsum[s0] += __expf(acc[mf][nf][0] * INV_T)
                                      + __expf(acc[mf][nf][1] * INV_T);
                            rsum[s1] += __expf(acc[mf][nf][2] * INV_T)
                                      + __expf(acc[mf][nf][3] * INV_T);
                        }
                    }
            }
        }

        // Direct-to-global writeback (overlaps next unit's prefetch fills).
        const int oseg = seg * 4 + wn;
#pragma unroll
        for (int s = 0; s < 8; ++s) {
            int row = wm * 64 + (s >> 1) * 16 + (lane >> 2) + (s & 1) * 8;
            if (isG1) {
                float vv = bestv[s];
                int ii = besti[s];
#pragma unroll
                for (int o = 1; o <= 2; o <<= 1) {
                    float ov = __shfl_xor_sync(0xffffffffu, vv, o);
                    int oi = __shfl_xor_sync(0xffffffffu, ii, o);
                    if (ov > vv || (ov == vv && oi < ii)) { vv = ov; ii = oi; }
                }
                if ((lane & 3) == 0) {
                    g_rowmax[(size_t)oseg * BB + row0 + row] = vv;
                    g_rowarg[(size_t)oseg * BB + row0 + row] = ii;
                }
            } else {
                float vv = rsum[s];
                vv += __shfl_xor_sync(0xffffffffu, vv, 1);
                vv += __shfl_xor_sync(0xffffffffu, vv, 2);
                if ((lane & 3) == 0)
                    g_centpart[(size_t)oseg * KK + row0 + row] = vv;
            }
        }

        __syncthreads();   // broadcast u_slot; all warps aligned to next unit
        ++k;
        u = *u_slot;
    }
}

// ---------------------------------------------------------------------------
// Per-sample loss: merge 32 disjoint-segment candidates per row (first-max
// semantics via (>, ==&&idx<)), add 32 centroid partial sums, reduce.
// ---------------------------------------------------------------------------
__global__ void k_finalj() {
    __shared__ float red[4];
    int i = blockIdx.x * 128 + threadIdx.x;
    float m = __int_as_float(0xff800000);
    int a = 0x7fffffff;
#pragma unroll 8
    for (int o = 0; o < OSEG; ++o) {
        float ms = g_rowmax[(size_t)o * BB + i];
        int as_ = g_rowarg[(size_t)o * BB + i];
        if (ms > m || (ms == m && as_ < a)) { m = ms; a = as_; }
    }
    float S = 0.0f;
#pragma unroll 8
    for (int o = 0; o < OSEG; ++o) S += g_centpart[(size_t)o * KK + a];
    float mt = m * INV_T;
    float J = mt - logf(expf(mt) + S);
    float s = J;
#pragma unroll
    for (int o = 16; o > 0; o >>= 1) s += __shfl_xor_sync(0xffffffffu, s, o);
    if ((threadIdx.x & 31) == 0) red[threadIdx.x >> 5] = s;
    __syncthreads();
    if (threadIdx.x == 0) g_jpart[blockIdx.x] = red[0] + red[1] + red[2] + red[3];
}

__global__ void k_reduce(float* out) {
    __shared__ float red[8];
    int t = threadIdx.x; // 256
    float s = g_jpart[t];
#pragma unroll
    for (int o = 16; o > 0; o >>= 1) s += __shfl_xor_sync(0xffffffffu, s, o);
    if ((t & 31) == 0) red[t >> 5] = s;
    __syncthreads();
    if (t == 0) {
        float tot = 0.0f;
        for (int i = 0; i < 8; ++i) tot += red[i];
        out[0] = -tot / (float)BB;
    }
}

// ---------------------------------------------------------------------------
extern "C" void kernel_launch(void* const* d_in, const int* in_sizes, int n_in,
                              void* d_out, int out_size) {
    const float* feat = (const float*)d_in[0];
    const float* cent = (const float*)d_in[1];
    if (n_in >= 2 && in_sizes[0] == KK * DD && in_sizes[1] == BB * DD) {
        feat = (const float*)d_in[1];
        cent = (const float*)d_in[0];
    }

    cudaFuncSetAttribute((const void*)gemm_all,
                         cudaFuncAttributeMaxDynamicSharedMemorySize, SMEM_TOTAL);

    k_prep_feat<<<3072, 256>>>(feat);
    k_prep_cent<<<KK, 128>>>(cent);
    gemm_all<<<152, 256, SMEM_TOTAL>>>();
    k_finalj<<<JBLOCKS, 128>>>();
    k_reduce<<<1, 256>>>((float*)d_out);
}

// round 15
// speedup vs baseline: 1.0664x; 1.0086x over previous
#include <cuda_runtime.h>
#include <cuda_bf16.h>
#include <cstdint>
#include <math.h>

// Problem constants
#define BB 32768
#define KK 8192
#define DD 384
#define JBLOCKS 256

constexpr float INV_T = 1.0f / 0.07f;

// Tiling: CTA tile 128x256, k-chunk 128; 8 warps as 2(M) x 4(N), warp tile 64x64
#define BM 128
#define BN 256
#define BKC 128
constexpr int A_UNITS = DD / 8;              // 48 16B-units per A row
constexpr int A_SEC_BYTES = BM * 16 * 16;    // 32768 per kc-section
constexpr int A_BYTES = 3 * A_SEC_BYTES;     // 98304 per stripe
constexpr int B_CHUNK = BN * BKC * 2;        // 65536 per chunk
constexpr int CTRL    = A_BYTES + 2 * B_CHUNK;  // 229376
constexpr int SMEM_TOTAL = CTRL + 128;          // 229504

// Work units: 4 n-tiles (1024 cols) of one 128-row stripe = 12 chunks.
//   u < 2048            : GEMM1 (feat x cent): stripe=u>>3, seg=u&7
//   2048 <= u < 2336    : GEMM2 (cent x cent), TRIANGLE ONLY:
//     enumerate (stripe I, seg) with seg >= floor(I/8); q-group sizes 8*(8-q).
//     Unit contributes: col-sums (always, -> g_centcol[I][cols in seg]) and
//     row-sums (only when seg > floor(I/8), -> g_centpart slot (seg*4+wn)).
//     Symmetry S[j] = sum_{qI<=qt} colsums + sum_{q>qt} rowsums covers all
//     sources exactly once (diagonal elements once, via col-sums).
#define NTILES 4
#define NCHUNK 12
#define G1UNITS 2048
#define G2UNITS 288
#define NUNITS  (G1UNITS + G2UNITS)
#define OSEG    32

// Pre-swizzled GMEM images + outputs (device globals: no allocation allowed)
// A images are SECTION-MAJOR: unit index = sec*2048 + r*16 + ((u&15)^(r&7)).
__device__ uint4 g_featS[BB * DD * 2 / 16];
__device__ uint4 g_centA[KK * DD * 2 / 16];
__device__ uint4 g_centB[KK * DD * 2 / 16];
__device__ float g_rowmax[(size_t)OSEG * BB];
__device__ int   g_rowarg[(size_t)OSEG * BB];
__device__ float g_centpart[(size_t)OSEG * KK];  // row-sum partials (pre-zeroed)
__device__ float g_centcol[(size_t)64 * KK];     // col-sum partials (pre-zeroed)
__device__ float g_jpart[JBLOCKS];
__device__ unsigned g_work;

// ---------------------------------------------------------------------------
__device__ __forceinline__ uint32_t smem_u32(const void* p) {
    return (uint32_t)__cvta_generic_to_shared(p);
}
__device__ __forceinline__ void mbar_init(uint32_t a, uint32_t c) {
    asm volatile("mbarrier.init.shared.b64 [%0], %1;" :: "r"(a), "r"(c) : "memory");
}
__device__ __forceinline__ void mbar_expect(uint32_t a, uint32_t bytes) {
    asm volatile("mbarrier.arrive.expect_tx.shared.b64 _, [%0], %1;"
                 :: "r"(a), "r"(bytes) : "memory");
}
__device__ __forceinline__ void bulk_g2s(uint32_t dst, const void* src,
                                         uint32_t bytes, uint32_t mb) {
    asm volatile(
        "cp.async.bulk.shared::cluster.global.mbarrier::complete_tx::bytes "
        "[%0], [%1], %2, [%3];"
        :: "r"(dst), "l"(src), "r"(bytes), "r"(mb) : "memory");
}
__device__ __forceinline__ void mbar_wait(uint32_t addr, uint32_t parity) {
    asm volatile(
        "{\n\t.reg .pred P;\n\t"
        "WL%=:\n\t"
        "mbarrier.try_wait.parity.acquire.cta.shared::cta.b64 P, [%0], %1, 0x989680;\n\t"
        "@P bra WD%=;\n\t"
        "bra WL%=;\n\t"
        "WD%=:\n\t}"
        :: "r"(addr), "r"(parity) : "memory");
}
__device__ __forceinline__ uint32_t atom_inc_acqrel(uint32_t addr) {
    uint32_t old;
    asm volatile("atom.add.acq_rel.cta.shared::cta.u32 %0, [%1], 1;"
                 : "=r"(old) : "r"(addr) : "memory");
    return old;
}
#define FENCE_ASYNC() asm volatile("fence.proxy.async.shared::cta;" ::: "memory")

__device__ __forceinline__ void ldsm4(uint32_t (&d)[4], uint32_t addr) {
    asm volatile("ldmatrix.sync.aligned.m8n8.x4.shared.b16 {%0,%1,%2,%3}, [%4];"
                 : "=r"(d[0]), "=r"(d[1]), "=r"(d[2]), "=r"(d[3]) : "r"(addr));
}

// Decode unit id -> (isG1, stripe, seg)
__device__ __forceinline__ void decode_unit(unsigned u, int& isG1,
                                            int& stripe, int& seg) {
    if (u < G1UNITS) {
        isG1 = 1; stripe = (int)u >> 3; seg = (int)u & 7;
    } else {
        isG1 = 0;
        int v = (int)u - G1UNITS, q = 0;
        while (v >= 8 * (8 - q)) { v -= 8 * (8 - q); ++q; }
        stripe = 8 * q + v / (8 - q);
        seg = q + v % (8 - q);
    }
}

// ---------------------------------------------------------------------------
// Prep: features fp32 -> bf16 section-major stripes. Zeros outputs + g_work.
// ---------------------------------------------------------------------------
__global__ void k_prep_feat(const float* __restrict__ feat) {
    if (blockIdx.x == 0 && threadIdx.x == 0) g_work = 0u;
    const int gstride = gridDim.x * blockDim.x;
    const int gid = blockIdx.x * blockDim.x + threadIdx.x;
    for (int i = gid; i < OSEG * KK; i += gstride) g_centpart[i] = 0.0f;
    for (int i = gid; i < 64 * KK; i += gstride) g_centcol[i] = 0.0f;
    const int NU = BB * A_UNITS;
    for (int idx = gid; idx < NU; idx += gstride) {
        int u = idx % A_UNITS;
        int r = (idx / A_UNITS) % BM;
        int s = idx / (A_UNITS * BM);
        const float4* src =
            (const float4*)(feat + (size_t)(s * BM + r) * DD + u * 8);
        float4 f0 = src[0], f1 = src[1];
        __nv_bfloat162 p0 = __floats2bfloat162_rn(f0.x, f0.y);
        __nv_bfloat162 p1 = __floats2bfloat162_rn(f0.z, f0.w);
        __nv_bfloat162 p2 = __floats2bfloat162_rn(f1.x, f1.y);
        __nv_bfloat162 p3 = __floats2bfloat162_rn(f1.z, f1.w);
        uint4 v;
        v.x = *(uint32_t*)&p0; v.y = *(uint32_t*)&p1;
        v.z = *(uint32_t*)&p2; v.w = *(uint32_t*)&p3;
        g_featS[s * (BM * A_UNITS) + (u >> 4) * (BM * 16)
                + r * 16 + ((u & 15) ^ (r & 7))] = v;
    }
}

// ---------------------------------------------------------------------------
// Prep: centroids normalize -> bf16 as section-major A stripes + B chunks.
// ---------------------------------------------------------------------------
__global__ void k_prep_cent(const float* __restrict__ cent) {
    __shared__ float red[4];
    int row = blockIdx.x, t = threadIdx.x;
    const float* src = cent + (size_t)row * DD;
    float v0 = src[t], v1 = src[t + 128], v2 = src[t + 256];
    float s = v0 * v0 + v1 * v1 + v2 * v2;
#pragma unroll
    for (int o = 16; o > 0; o >>= 1) s += __shfl_xor_sync(0xffffffffu, s, o);
    if ((t & 31) == 0) red[t >> 5] = s;
    __syncthreads();
    float inv = 1.0f / fmaxf(sqrtf(red[0] + red[1] + red[2] + red[3]), 1e-12f);

    int j = -1;
    if (t < 48) j = t;
    else if (t >= 64 && t < 112) j = t - 64;
    if (j >= 0) {
        const float4* sp = (const float4*)(src + j * 8);
        float4 f0 = sp[0], f1 = sp[1];
        __nv_bfloat162 p0 = __floats2bfloat162_rn(f0.x * inv, f0.y * inv);
        __nv_bfloat162 p1 = __floats2bfloat162_rn(f0.z * inv, f0.w * inv);
        __nv_bfloat162 p2 = __floats2bfloat162_rn(f1.x * inv, f1.y * inv);
        __nv_bfloat162 p3 = __floats2bfloat162_rn(f1.z * inv, f1.w * inv);
        uint4 v;
        v.x = *(uint32_t*)&p0; v.y = *(uint32_t*)&p1;
        v.z = *(uint32_t*)&p2; v.w = *(uint32_t*)&p3;
        if (t < 48) {
            int sA = row >> 7, r = row & 127;
            g_centA[sA * (BM * A_UNITS) + (j >> 4) * (BM * 16)
                    + r * 16 + ((j & 15) ^ (r & 7))] = v;
        } else {
            int nt = row >> 8, rr = row & 255, kc = j >> 4, uu = j & 15;
            g_centB[(size_t)(nt * 3 + kc) * 4096 + rr * 16 + (uu ^ (rr & 7))] = v;
        }
    }
}

// ---------------------------------------------------------------------------
// Persistent fused GEMM (152 CTAs, never-drain pipeline). GEMM2 computes the
// upper triangle only (288 units); its epilogue emits row sums AND exact
// 128-row column sums (shfl reduce + 2-source deterministic RED.ADD).
// ---------------------------------------------------------------------------
__global__ void __launch_bounds__(256, 1) gemm_all() {
    extern __shared__ char smem[];
    const int tid = threadIdx.x, lane = tid & 31, wid = tid >> 5;
    const int wm = wid >> 2, wn = wid & 3;
    const uint32_t sb = smem_u32(smem);
    const uint32_t mbA = sb + CTRL;          // A section mbars[3]
    const uint32_t mbF = sb + CTRL + 24;     // B full mbars[2]
    const uint32_t cnt = sb + CTRL + 40;     // 12 monotonic u32 counters
    uint32_t* const u_slot = (uint32_t*)(smem + CTRL + 88);

    auto issueA = [&](unsigned uu, int sec) {
        int g1, stripe, seg;
        decode_unit(uu, g1, stripe, seg);
        const uint4* src = (g1 ? g_featS : g_centA)
                         + (size_t)stripe * (BM * A_UNITS) + sec * (BM * 16);
        mbar_expect(mbA + sec * 8, A_SEC_BYTES);
        bulk_g2s(sb + sec * A_SEC_BYTES, src, A_SEC_BYTES, mbA + sec * 8);
    };
    auto issueB = [&](unsigned uu, int c) {
        int g1, stripe, seg;
        decode_unit(uu, g1, stripe, seg);
        const uint4* src =
            g_centB + (size_t)((seg * NTILES + c / 3) * 3 + c % 3) * 4096;
        int slot = c & 1;
        mbar_expect(mbF + slot * 8, B_CHUNK);
        bulk_g2s(sb + A_BYTES + slot * B_CHUNK, src, B_CHUNK, mbF + slot * 8);
    };

    if (tid == 0) {
        mbar_init(mbA, 1); mbar_init(mbA + 8, 1); mbar_init(mbA + 16, 1);
        mbar_init(mbF, 1); mbar_init(mbF + 8, 1);
        *u_slot = atomicAdd(&g_work, 1u);
    }
    if (tid < NCHUNK) *(uint32_t*)(smem + CTRL + 40 + tid * 4) = 0u;
    __syncthreads();

    unsigned u = *u_slot;
    int k = 0;
    if (tid == 0 && u < NUNITS) {
        issueA(u, 0); issueA(u, 1); issueA(u, 2);
        issueB(u, 0); issueB(u, 1);
    }

    while (u < NUNITS) {
        int isG1, stripe, seg;
        decode_unit(u, isG1, stripe, seg);
        const int row0 = stripe * BM;
        const int col_begin = seg * (NTILES * BN);

        float acc[4][8][4];
        float bestv[8];
        int   besti[8];
        float rsum[8];
#pragma unroll
        for (int s = 0; s < 8; ++s) {
            bestv[s] = __int_as_float(0xff800000);
            besti[s] = 0x7fffffff;
            rsum[s]  = 0.0f;
        }

        for (int c = 0; c < NCHUNK; ++c) {
            const int slot = c & 1, kc = c % 3, nt = c / 3;
            if (c < 3) mbar_wait(mbA + c * 8, (uint32_t)(k & 1));
            mbar_wait(mbF + slot * 8, (uint32_t)((c >> 1) & 1));
            const uint32_t bbase = sb + A_BYTES + slot * B_CHUNK;
            const uint32_t abase = sb + kc * A_SEC_BYTES;

            if (kc == 0) {
#pragma unroll
                for (int mf = 0; mf < 4; ++mf)
#pragma unroll
                    for (int nf = 0; nf < 8; ++nf)
#pragma unroll
                        for (int q = 0; q < 4; ++q) acc[mf][nf][q] = 0.0f;
            }

#pragma unroll
            for (int ks = 0; ks < 8; ++ks) {
                uint32_t a[4][4], b[4][4];
#pragma unroll
                for (int mf = 0; mf < 4; ++mf) {
                    int r = wm * 64 + mf * 16 + (lane & 15);
                    int ul = ks * 2 + (lane >> 4);
                    ldsm4(a[mf],
                          abase + (uint32_t)(r * 16 + (ul ^ (r & 7))) * 16u);
                }
#pragma unroll
                for (int np = 0; np < 4; ++np) {
                    int r = wn * 64 + np * 16 + (lane & 7) + ((lane >> 4) << 3);
                    int uu = ks * 2 + ((lane >> 3) & 1);
                    ldsm4(b[np],
                          bbase + (uint32_t)(r * 16 + (uu ^ (r & 7))) * 16u);
                }
#pragma unroll
                for (int mf = 0; mf < 4; ++mf)
#pragma unroll
                    for (int nf = 0; nf < 8; ++nf) {
                        int np = nf >> 1, h = nf & 1;
                        asm volatile(
                            "mma.sync.aligned.m16n8k16.row.col.f32.bf16.bf16.f32 "
                            "{%0,%1,%2,%3}, {%4,%5,%6,%7}, {%8,%9}, {%0,%1,%2,%3};\n"
                            : "+f"(acc[mf][nf][0]), "+f"(acc[mf][nf][1]),
                              "+f"(acc[mf][nf][2]), "+f"(acc[mf][nf][3])
                            : "r"(a[mf][0]), "r"(a[mf][1]), "r"(a[mf][2]),
                              "r"(a[mf][3]),
                              "r"(b[np][h * 2]), "r"(b[np][h * 2 + 1]));
                    }
            }

            // Buffer release + refill/prefetch by the LAST finisher of chunk c.
            if (lane == 0) {
                uint32_t old = atom_inc_acqrel(cnt + c * 4);
                if (old == (uint32_t)(8 * k + 7)) {
                    FENCE_ASYNC();
                    if (c <= NCHUNK - 3) issueB(u, c + 2);
                    if (c == 8) {
                        *u_slot = atomicAdd(&g_work, 1u);   // grab next unit
                    } else if (c == 9) {
                        unsigned un = *u_slot;
                        if (un < NUNITS) issueA(un, 0);
                    } else if (c == 10) {
                        unsigned un = *u_slot;
                        if (un < NUNITS) { issueA(un, 1); issueB(un, 0); }
                    } else if (c == 11) {
                        unsigned un = *u_slot;
                        if (un < NUNITS) { issueA(un, 2); issueB(un, 1); }
                    }
                }
            }

            if (kc == 2) {
                int cbase = col_begin + nt * BN + wn * 64 + 2 * (lane & 3);
                if (isG1) {
#pragma unroll
                    for (int mf = 0; mf < 4; ++mf)
#pragma unroll
                        for (int nf = 0; nf < 8; ++nf) {
                            int col = cbase + nf * 8;
                            int s0 = mf * 2, s1 = mf * 2 + 1;
                            float v0 = acc[mf][nf][0], v1 = acc[mf][nf][1];
                            float v2 = acc[mf][nf][2], v3 = acc[mf][nf][3];
                            if (v0 > bestv[s0]) { bestv[s0] = v0; besti[s0] = col; }
                            if (v1 > bestv[s0]) { bestv[s0] = v1; besti[s0] = col + 1; }
                            if (v2 > bestv[s1]) { bestv[s1] = v2; besti[s1] = col; }
                            if (v3 > bestv[s1]) { bestv[s1] = v3; besti[s1] = col + 1; }
                        }
                } else {
                    // Row sums AND 128-row column sums for this 128x256 tile.
                    float csum[16];
#pragma unroll
                    for (int jj = 0; jj < 16; ++jj) csum[jj] = 0.0f;
#pragma unroll
                    for (int mf = 0; mf < 4; ++mf)
#pragma unroll
                        for (int nf = 0; nf < 8; ++nf) {
                            int s0 = mf * 2, s1 = mf * 2 + 1;
                            float e0 = __expf(acc[mf][nf][0] * INV_T);
                            float e1 = __expf(acc[mf][nf][1] * INV_T);
                            float e2 = __expf(acc[mf][nf][2] * INV_T);
                            float e3 = __expf(acc[mf][nf][3] * INV_T);
                            rsum[s0] += e0 + e1;
                            rsum[s1] += e2 + e3;
                            csum[nf * 2]     += e0 + e2;
                            csum[nf * 2 + 1] += e1 + e3;
                        }
#pragma unroll
                    for (int jj = 0; jj < 16; ++jj) {
                        float v = csum[jj];
                        v += __shfl_xor_sync(0xffffffffu, v, 4);
                        v += __shfl_xor_sync(0xffffffffu, v, 8);
                        v += __shfl_xor_sync(0xffffffffu, v, 16);
                        if (lane < 4) {
                            int col = cbase + (jj >> 1) * 8 + (jj & 1);
                            // exactly 2 adders per slot (wm=0, wm=1): a+b is
                            // order-independent -> deterministic
                            atomicAdd(&g_centcol[(size_t)stripe * KK + col], v);
                        }
                    }
                }
            }
        }

        // Direct-to-global writeback (overlaps next unit's prefetch fills).
        const int oseg = seg * 4 + wn;
#pragma unroll
        for (int s = 0; s < 8; ++s) {
            int row = wm * 64 + (s >> 1) * 16 + (lane >> 2) + (s & 1) * 8;
            if (isG1) {
                float vv = bestv[s];
                int ii = besti[s];
#pragma unroll
                for (int o = 1; o <= 2; o <<= 1) {
                    float ov = __shfl_xor_sync(0xffffffffu, vv, o);
                    int oi = __shfl_xor_sync(0xffffffffu, ii, o);
                    if (ov > vv || (ov == vv && oi < ii)) { vv = ov; ii = oi; }
                }
                if ((lane & 3) == 0) {
                    g_rowmax[(size_t)oseg * BB + row0 + row] = vv;
                    g_rowarg[(size_t)oseg * BB + row0 + row] = ii;
                }
            } else if (seg > (stripe >> 3)) {   // diagonal units: row sums unused
                float vv = rsum[s];
                vv += __shfl_xor_sync(0xffffffffu, vv, 1);
                vv += __shfl_xor_sync(0xffffffffu, vv, 2);
                if ((lane & 3) == 0)
                    g_centpart[(size_t)oseg * KK + row0 + row] = vv;
            }
        }

        __syncthreads();   // broadcast u_slot; all warps aligned to next unit
        ++k;
        u = *u_slot;
    }
}

// ---------------------------------------------------------------------------
// Per-sample loss: merge 32 candidates/row; S = 32 row-sum partials + 64
// col-sum partials at the argmax column; reduce.
// ---------------------------------------------------------------------------
__global__ void k_finalj() {
    __shared__ float red[4];
    int i = blockIdx.x * 128 + threadIdx.x;
    float m = __int_as_float(0xff800000);
    int a = 0x7fffffff;
#pragma unroll 8
    for (int o = 0; o < OSEG; ++o) {
        float ms = g_rowmax[(size_t)o * BB + i];
        int as_ = g_rowarg[(size_t)o * BB + i];
        if (ms > m || (ms == m && as_ < a)) { m = ms; a = as_; }
    }
    float S = 0.0f;
#pragma unroll 8
    for (int o = 0; o < OSEG; ++o) S += g_centpart[(size_t)o * KK + a];
#pragma unroll 8
    for (int o = 0; o < 64; ++o) S += g_centcol[(size_t)o * KK + a];
    float mt = m * INV_T;
    float J = mt - logf(expf(mt) + S);
    float s = J;
#pragma unroll
    for (int o = 16; o > 0; o >>= 1) s += __shfl_xor_sync(0xffffffffu, s, o);
    if ((threadIdx.x & 31) == 0) red[threadIdx.x >> 5] = s;
    __syncthreads();
    if (threadIdx.x == 0) g_jpart[blockIdx.x] = red[0] + red[1] + red[2] + red[3];
}

__global__ void k_reduce(float* out) {
    __shared__ float red[8];
    int t = threadIdx.x; // 256
    float s = g_jpart[t];
#pragma unroll
    for (int o = 16; o > 0; o >>= 1) s += __shfl_xor_sync(0xffffffffu, s, o);
    if ((t & 31) == 0) red[t >> 5] = s;
    __syncthreads();
    if (t == 0) {
        float tot = 0.0f;
        for (int i = 0; i < 8; ++i) tot += red[i];
        out[0] = -tot / (float)BB;
    }
}

// ---------------------------------------------------------------------------
extern "C" void kernel_launch(void* const* d_in, const int* in_sizes, int n_in,
                              void* d_out, int out_size) {
    const float* feat = (const float*)d_in[0];
    const float* cent = (const float*)d_in[1];
    if (n_in >= 2 && in_sizes[0] == KK * DD && in_sizes[1] == BB * DD) {
        feat = (const float*)d_in[1];
        cent = (const float*)d_in[0];
    }

    cudaFuncSetAttribute((const void*)gemm_all,
                         cudaFuncAttributeMaxDynamicSharedMemorySize, SMEM_TOTAL);

    k_prep_feat<<<3072, 256>>>(feat);
    k_prep_cent<<<KK, 128>>>(cent);
    gemm_all<<<152, 256, SMEM_TOTAL>>>();
    k_finalj<<<JBLOCKS, 128>>>();
    k_reduce<<<1, 256>>>((float*)d_out);
}

// round 16
// speedup vs baseline: 1.0702x; 1.0036x over previous
#include <cuda_runtime.h>
#include <cuda_bf16.h>
#include <cstdint>
#include <math.h>

// Problem constants
#define BB 32768
#define KK 8192
#define DD 384
#define JBLOCKS 256

constexpr float INV_T = 1.0f / 0.07f;

// Tiling: CTA tile 128x256, k-chunk 128; 8 warps as 2(M) x 4(N), warp tile 64x64
#define BM 128
#define BN 256
#define BKC 128
constexpr int A_UNITS = DD / 8;              // 48 16B-units per A row
constexpr int A_SEC_BYTES = BM * 16 * 16;    // 32768 per kc-section
constexpr int A_BYTES = 3 * A_SEC_BYTES;     // 98304 per stripe
constexpr int B_CHUNK = BN * BKC * 2;        // 65536 per chunk
constexpr int CTRL    = A_BYTES + 2 * B_CHUNK;  // 229376
constexpr int SMEM_TOTAL = CTRL + 128;          // 229504

// Work units: 4 n-tiles (1024 cols) of one 128-row stripe = 12 chunks.
//   u < 2048         : GEMM1 (feat x cent): stripe=u>>3, seg=u&7
//   2048 <= u < 2336 : GEMM2 (cent x cent), TRIANGLE ONLY (seg >= floor(I/8)).
//     col-sums always -> g_centcol[I][.]; row-sums only when seg > floor(I/8).
#define NTILES 4
#define NCHUNK 12
#define G1UNITS 2048
#define G2UNITS 288
#define NUNITS  (G1UNITS + G2UNITS)
#define OSEG    32

// Pre-swizzled GMEM images + outputs (device globals: no allocation allowed)
// A images are SECTION-MAJOR: unit index = sec*2048 + r*16 + ((u&15)^(r&7)).
__device__ uint4 g_featS[BB * DD * 2 / 16];
__device__ uint4 g_centA[KK * DD * 2 / 16];
__device__ uint4 g_centB[KK * DD * 2 / 16];
__device__ float g_rowmax[(size_t)OSEG * BB];
__device__ int   g_rowarg[(size_t)OSEG * BB];
__device__ float g_centpart[(size_t)OSEG * KK];  // row-sum partials (pre-zeroed)
__device__ float g_centcol[(size_t)64 * KK];     // col-sum partials (pre-zeroed)
__device__ float g_S[KK];                        // folded centroid sums
__device__ float g_jpart[JBLOCKS];
__device__ unsigned g_work;

// ---------------------------------------------------------------------------
__device__ __forceinline__ uint32_t smem_u32(const void* p) {
    return (uint32_t)__cvta_generic_to_shared(p);
}
__device__ __forceinline__ void mbar_init(uint32_t a, uint32_t c) {
    asm volatile("mbarrier.init.shared.b64 [%0], %1;" :: "r"(a), "r"(c) : "memory");
}
__device__ __forceinline__ void mbar_expect(uint32_t a, uint32_t bytes) {
    asm volatile("mbarrier.arrive.expect_tx.shared.b64 _, [%0], %1;"
                 :: "r"(a), "r"(bytes) : "memory");
}
__device__ __forceinline__ void bulk_g2s(uint32_t dst, const void* src,
                                         uint32_t bytes, uint32_t mb) {
    asm volatile(
        "cp.async.bulk.shared::cluster.global.mbarrier::complete_tx::bytes "
        "[%0], [%1], %2, [%3];"
        :: "r"(dst), "l"(src), "r"(bytes), "r"(mb) : "memory");
}
__device__ __forceinline__ void mbar_wait(uint32_t addr, uint32_t parity) {
    asm volatile(
        "{\n\t.reg .pred P;\n\t"
        "WL%=:\n\t"
        "mbarrier.try_wait.parity.acquire.cta.shared::cta.b64 P, [%0], %1, 0x989680;\n\t"
        "@P bra WD%=;\n\t"
        "bra WL%=;\n\t"
        "WD%=:\n\t}"
        :: "r"(addr), "r"(parity) : "memory");
}
__device__ __forceinline__ uint32_t atom_inc_acqrel(uint32_t addr) {
    uint32_t old;
    asm volatile("atom.add.acq_rel.cta.shared::cta.u32 %0, [%1], 1;"
                 : "=r"(old) : "r"(addr) : "memory");
    return old;
}
#define FENCE_ASYNC() asm volatile("fence.proxy.async.shared::cta;" ::: "memory")

__device__ __forceinline__ void ldsm4(uint32_t (&d)[4], uint32_t addr) {
    asm volatile("ldmatrix.sync.aligned.m8n8.x4.shared.b16 {%0,%1,%2,%3}, [%4];"
                 : "=r"(d[0]), "=r"(d[1]), "=r"(d[2]), "=r"(d[3]) : "r"(addr));
}

// Decode unit id -> (isG1, stripe, seg)
__device__ __forceinline__ void decode_unit(unsigned u, int& isG1,
                                            int& stripe, int& seg) {
    if (u < G1UNITS) {
        isG1 = 1; stripe = (int)u >> 3; seg = (int)u & 7;
    } else {
        isG1 = 0;
        int v = (int)u - G1UNITS, q = 0;
        while (v >= 8 * (8 - q)) { v -= 8 * (8 - q); ++q; }
        stripe = 8 * q + v / (8 - q);
        seg = q + v % (8 - q);
    }
}

// One ks step: 8 ldmatrix + 32 mma. ZC=true: first step of a tile, C=0
// (writes acc fresh -> no accumulator zero-fill loop needed).
template <bool ZC>
__device__ __forceinline__ void ks_step(int ks, uint32_t abase, uint32_t bbase,
                                        int wm, int wn, int lane,
                                        float (&acc)[4][8][4]) {
    uint32_t a[4][4], b[4][4];
#pragma unroll
    for (int mf = 0; mf < 4; ++mf) {
        int r = wm * 64 + mf * 16 + (lane & 15);
        int ul = ks * 2 + (lane >> 4);
        ldsm4(a[mf], abase + (uint32_t)(r * 16 + (ul ^ (r & 7))) * 16u);
    }
#pragma unroll
    for (int np = 0; np < 4; ++np) {
        int r = wn * 64 + np * 16 + (lane & 7) + ((lane >> 4) << 3);
        int uu = ks * 2 + ((lane >> 3) & 1);
        ldsm4(b[np], bbase + (uint32_t)(r * 16 + (uu ^ (r & 7))) * 16u);
    }
#pragma unroll
    for (int mf = 0; mf < 4; ++mf)
#pragma unroll
        for (int nf = 0; nf < 8; ++nf) {
            int np = nf >> 1, h = nf & 1;
            if (ZC) {
                asm volatile(
                    "mma.sync.aligned.m16n8k16.row.col.f32.bf16.bf16.f32 "
                    "{%0,%1,%2,%3}, {%4,%5,%6,%7}, {%8,%9}, {%10,%11,%12,%13};\n"
                    : "=f"(acc[mf][nf][0]), "=f"(acc[mf][nf][1]),
                      "=f"(acc[mf][nf][2]), "=f"(acc[mf][nf][3])
                    : "r"(a[mf][0]), "r"(a[mf][1]), "r"(a[mf][2]), "r"(a[mf][3]),
                      "r"(b[np][h * 2]), "r"(b[np][h * 2 + 1]),
                      "f"(0.0f), "f"(0.0f), "f"(0.0f), "f"(0.0f));
            } else {
                asm volatile(
                    "mma.sync.aligned.m16n8k16.row.col.f32.bf16.bf16.f32 "
                    "{%0,%1,%2,%3}, {%4,%5,%6,%7}, {%8,%9}, {%0,%1,%2,%3};\n"
                    : "+f"(acc[mf][nf][0]), "+f"(acc[mf][nf][1]),
                      "+f"(acc[mf][nf][2]), "+f"(acc[mf][nf][3])
                    : "r"(a[mf][0]), "r"(a[mf][1]), "r"(a[mf][2]), "r"(a[mf][3]),
                      "r"(b[np][h * 2]), "r"(b[np][h * 2 + 1]));
            }
        }
}

// ---------------------------------------------------------------------------
// Prep: features fp32 -> bf16 section-major stripes. Zeros outputs + g_work.
// ---------------------------------------------------------------------------
__global__ void k_prep_feat(const float* __restrict__ feat) {
    if (blockIdx.x == 0 && threadIdx.x == 0) g_work = 0u;
    const int gstride = gridDim.x * blockDim.x;
    const int gid = blockIdx.x * blockDim.x + threadIdx.x;
    for (int i = gid; i < OSEG * KK; i += gstride) g_centpart[i] = 0.0f;
    for (int i = gid; i < 64 * KK; i += gstride) g_centcol[i] = 0.0f;
    const int NU = BB * A_UNITS;
    for (int idx = gid; idx < NU; idx += gstride) {
        int u = idx % A_UNITS;
        int r = (idx / A_UNITS) % BM;
        int s = idx / (A_UNITS * BM);
        const float4* src =
            (const float4*)(feat + (size_t)(s * BM + r) * DD + u * 8);
        float4 f0 = src[0], f1 = src[1];
        __nv_bfloat162 p0 = __floats2bfloat162_rn(f0.x, f0.y);
        __nv_bfloat162 p1 = __floats2bfloat162_rn(f0.z, f0.w);
        __nv_bfloat162 p2 = __floats2bfloat162_rn(f1.x, f1.y);
        __nv_bfloat162 p3 = __floats2bfloat162_rn(f1.z, f1.w);
        uint4 v;
        v.x = *(uint32_t*)&p0; v.y = *(uint32_t*)&p1;
        v.z = *(uint32_t*)&p2; v.w = *(uint32_t*)&p3;
        g_featS[s * (BM * A_UNITS) + (u >> 4) * (BM * 16)
                + r * 16 + ((u & 15) ^ (r & 7))] = v;
    }
}

// ---------------------------------------------------------------------------
// Prep: centroids normalize -> bf16 as section-major A stripes + B chunks.
// ---------------------------------------------------------------------------
__global__ void k_prep_cent(const float* __restrict__ cent) {
    __shared__ float red[4];
    int row = blockIdx.x, t = threadIdx.x;
    const float* src = cent + (size_t)row * DD;
    float v0 = src[t], v1 = src[t + 128], v2 = src[t + 256];
    float s = v0 * v0 + v1 * v1 + v2 * v2;
#pragma unroll
    for (int o = 16; o > 0; o >>= 1) s += __shfl_xor_sync(0xffffffffu, s, o);
    if ((t & 31) == 0) red[t >> 5] = s;
    __syncthreads();
    float inv = 1.0f / fmaxf(sqrtf(red[0] + red[1] + red[2] + red[3]), 1e-12f);

    int j = -1;
    if (t < 48) j = t;
    else if (t >= 64 && t < 112) j = t - 64;
    if (j >= 0) {
        const float4* sp = (const float4*)(src + j * 8);
        float4 f0 = sp[0], f1 = sp[1];
        __nv_bfloat162 p0 = __floats2bfloat162_rn(f0.x * inv, f0.y * inv);
        __nv_bfloat162 p1 = __floats2bfloat162_rn(f0.z * inv, f0.w * inv);
        __nv_bfloat162 p2 = __floats2bfloat162_rn(f1.x * inv, f1.y * inv);
        __nv_bfloat162 p3 = __floats2bfloat162_rn(f1.z * inv, f1.w * inv);
        uint4 v;
        v.x = *(uint32_t*)&p0; v.y = *(uint32_t*)&p1;
        v.z = *(uint32_t*)&p2; v.w = *(uint32_t*)&p3;
        if (t < 48) {
            int sA = row >> 7, r = row & 127;
            g_centA[sA * (BM * A_UNITS) + (j >> 4) * (BM * 16)
                    + r * 16 + ((j & 15) ^ (r & 7))] = v;
        } else {
            int nt = row >> 8, rr = row & 255, kc = j >> 4, uu = j & 15;
            g_centB[(size_t)(nt * 3 + kc) * 4096 + rr * 16 + (uu ^ (rr & 7))] = v;
        }
    }
}

// ---------------------------------------------------------------------------
// Persistent fused GEMM (152 CTAs, never-drain pipeline). GEMM2 = upper
// triangle only; epilogue emits row sums AND exact 128-row column sums.
// ---------------------------------------------------------------------------
__global__ void __launch_bounds__(256, 1) gemm_all() {
    extern __shared__ char smem[];
    const int tid = threadIdx.x, lane = tid & 31, wid = tid >> 5;
    const int wm = wid >> 2, wn = wid & 3;
    const uint32_t sb = smem_u32(smem);
    const uint32_t mbA = sb + CTRL;          // A section mbars[3]
    const uint32_t mbF = sb + CTRL + 24;     // B full mbars[2]
    const uint32_t cnt = sb + CTRL + 40;     // 12 monotonic u32 counters
    uint32_t* const u_slot = (uint32_t*)(smem + CTRL + 88);

    auto issueA = [&](unsigned uu, int sec) {
        int g1, stripe, seg;
        decode_unit(uu, g1, stripe, seg);
        const uint4* src = (g1 ? g_featS : g_centA)
                         + (size_t)stripe * (BM * A_UNITS) + sec * (BM * 16);
        mbar_expect(mbA + sec * 8, A_SEC_BYTES);
        bulk_g2s(sb + sec * A_SEC_BYTES, src, A_SEC_BYTES, mbA + sec * 8);
    };
    auto issueB = [&](unsigned uu, int c) {
        int g1, stripe, seg;
        decode_unit(uu, g1, stripe, seg);
        const uint4* src =
            g_centB + (size_t)((seg * NTILES + c / 3) * 3 + c % 3) * 4096;
        int slot = c & 1;
        mbar_expect(mbF + slot * 8, B_CHUNK);
        bulk_g2s(sb + A_BYTES + slot * B_CHUNK, src, B_CHUNK, mbF + slot * 8);
    };

    if (tid == 0) {
        mbar_init(mbA, 1); mbar_init(mbA + 8, 1); mbar_init(mbA + 16, 1);
        mbar_init(mbF, 1); mbar_init(mbF + 8, 1);
        *u_slot = atomicAdd(&g_work, 1u);
    }
    if (tid < NCHUNK) *(uint32_t*)(smem + CTRL + 40 + tid * 4) = 0u;
    __syncthreads();

    unsigned u = *u_slot;
    int k = 0;
    if (tid == 0 && u < NUNITS) {
        issueA(u, 0); issueA(u, 1); issueA(u, 2);
        issueB(u, 0); issueB(u, 1);
    }

    while (u < NUNITS) {
        int isG1, stripe, seg;
        decode_unit(u, isG1, stripe, seg);
        const int row0 = stripe * BM;
        const int col_begin = seg * (NTILES * BN);

        float acc[4][8][4];
        float bestv[8];
        int   besti[8];
        float rsum[8];
#pragma unroll
        for (int s = 0; s < 8; ++s) {
            bestv[s] = __int_as_float(0xff800000);
            besti[s] = 0x7fffffff;
            rsum[s]  = 0.0f;
        }

        for (int c = 0; c < NCHUNK; ++c) {
            const int slot = c & 1, kc = c % 3, nt = c / 3;
            if (c < 3) mbar_wait(mbA + c * 8, (uint32_t)(k & 1));
            mbar_wait(mbF + slot * 8, (uint32_t)((c >> 1) & 1));
            const uint32_t bbase = sb + A_BYTES + slot * B_CHUNK;
            const uint32_t abase = sb + kc * A_SEC_BYTES;

            if (kc == 0) {
                ks_step<true>(0, abase, bbase, wm, wn, lane, acc);
#pragma unroll
                for (int ks = 1; ks < 8; ++ks)
                    ks_step<false>(ks, abase, bbase, wm, wn, lane, acc);
            } else {
#pragma unroll
                for (int ks = 0; ks < 8; ++ks)
                    ks_step<false>(ks, abase, bbase, wm, wn, lane, acc);
            }

            // Buffer release + refill/prefetch by the LAST finisher of chunk c.
            if (lane == 0) {
                uint32_t old = atom_inc_acqrel(cnt + c * 4);
                if (old == (uint32_t)(8 * k + 7)) {
                    FENCE_ASYNC();
                    if (c <= NCHUNK - 3) issueB(u, c + 2);
                    if (c == 8) {
                        *u_slot = atomicAdd(&g_work, 1u);   // grab next unit
                    } else if (c == 9) {
                        unsigned un = *u_slot;
                        if (un < NUNITS) issueA(un, 0);
                    } else if (c == 10) {
                        unsigned un = *u_slot;
                        if (un < NUNITS) { issueA(un, 1); issueB(un, 0); }
                    } else if (c == 11) {
                        unsigned un = *u_slot;
                        if (un < NUNITS) { issueA(un, 2); issueB(un, 1); }
                    }
                }
            }

            if (kc == 2) {
                int cbase = col_begin + nt * BN + wn * 64 + 2 * (lane & 3);
                if (isG1) {
#pragma unroll
                    for (int mf = 0; mf < 4; ++mf)
#pragma unroll
                        for (int nf = 0; nf < 8; ++nf) {
                            int col = cbase + nf * 8;
                            int s0 = mf * 2, s1 = mf * 2 + 1;
                            float v0 = acc[mf][nf][0], v1 = acc[mf][nf][1];
                            float v2 = acc[mf][nf][2], v3 = acc[mf][nf][3];
                            if (v0 > bestv[s0]) { bestv[s0] = v0; besti[s0] = col; }
                            if (v1 > bestv[s0]) { bestv[s0] = v1; besti[s0] = col + 1; }
                            if (v2 > bestv[s1]) { bestv[s1] = v2; besti[s1] = col; }
                            if (v3 > bestv[s1]) { bestv[s1] = v3; besti[s1] = col + 1; }
                        }
                } else {
                    // Row sums AND 128-row column sums for this 128x256 tile.
                    float csum[16];
#pragma unroll
                    for (int jj = 0; jj < 16; ++jj) csum[jj] = 0.0f;
#pragma unroll
                    for (int mf = 0; mf < 4; ++mf)
#pragma unroll
                        for (int nf = 0; nf < 8; ++nf) {
                            int s0 = mf * 2, s1 = mf * 2 + 1;
                            float e0 = __expf(acc[mf][nf][0] * INV_T);
                            float e1 = __expf(acc[mf][nf][1] * INV_T);
                            float e2 = __expf(acc[mf][nf][2] * INV_T);
                            float e3 = __expf(acc[mf][nf][3] * INV_T);
                            rsum[s0] += e0 + e1;
                            rsum[s1] += e2 + e3;
                            csum[nf * 2]     += e0 + e2;
                            csum[nf * 2 + 1] += e1 + e3;
                        }
#pragma unroll
                    for (int jj = 0; jj < 16; ++jj) {
                        float v = csum[jj];
                        v += __shfl_xor_sync(0xffffffffu, v, 4);
                        v += __shfl_xor_sync(0xffffffffu, v, 8);
                        v += __shfl_xor_sync(0xffffffffu, v, 16);
                        if (lane < 4) {
                            int col = cbase + (jj >> 1) * 8 + (jj & 1);
                            // exactly 2 adders per slot (wm=0, wm=1): a+b is
                            // order-independent -> deterministic
                            atomicAdd(&g_centcol[(size_t)stripe * KK + col], v);
                        }
                    }
                }
            }
        }

        // Direct-to-global writeback (overlaps next unit's prefetch fills).
        const int oseg = seg * 4 + wn;
#pragma unroll
        for (int s = 0; s < 8; ++s) {
            int row = wm * 64 + (s >> 1) * 16 + (lane >> 2) + (s & 1) * 8;
            if (isG1) {
                float vv = bestv[s];
                int ii = besti[s];
#pragma unroll
                for (int o = 1; o <= 2; o <<= 1) {
                    float ov = __shfl_xor_sync(0xffffffffu, vv, o);
                    int oi = __shfl_xor_sync(0xffffffffu, ii, o);
                    if (ov > vv || (ov == vv && oi < ii)) { vv = ov; ii = oi; }
                }
                if ((lane & 3) == 0) {
                    g_rowmax[(size_t)oseg * BB + row0 + row] = vv;
                    g_rowarg[(size_t)oseg * BB + row0 + row] = ii;
                }
            } else if (seg > (stripe >> 3)) {   // diagonal units: row sums unused
                float vv = rsum[s];
                vv += __shfl_xor_sync(0xffffffffu, vv, 1);
                vv += __shfl_xor_sync(0xffffffffu, vv, 2);
                if ((lane & 3) == 0)
                    g_centpart[(size_t)oseg * KK + row0 + row] = vv;
            }
        }

        __syncthreads();   // broadcast u_slot; all warps aligned to next unit
        ++k;
        u = *u_slot;
    }
}

// ---------------------------------------------------------------------------
// Fold S[j] = sum of 32 row-sum + 64 col-sum partials (same order as before).
// ---------------------------------------------------------------------------
__global__ void k_sumS() {
    int j = blockIdx.x * blockDim.x + threadIdx.x;  // 8192 threads
    float S = 0.0f;
#pragma unroll 8
    for (int o = 0; o < OSEG; ++o) S += g_centpart[(size_t)o * KK + j];
#pragma unroll 8
    for (int o = 0; o < 64; ++o) S += g_centcol[(size_t)o * KK + j];
    g_S[j] = S;
}

// ---------------------------------------------------------------------------
// Per-sample loss: merge 32 candidates/row; single gather of S[a]; reduce.
// ---------------------------------------------------------------------------
__global__ void k_finalj() {
    __shared__ float red[4];
    int i = blockIdx.x * 128 + threadIdx.x;
    float m = __int_as_float(0xff800000);
    int a = 0x7fffffff;
#pragma unroll 8
    for (int o = 0; o < OSEG; ++o) {
        float ms = g_rowmax[(size_t)o * BB + i];
        int as_ = g_rowarg[(size_t)o * BB + i];
        if (ms > m || (ms == m && as_ < a)) { m = ms; a = as_; }
    }
    float S = g_S[a];
    float mt = m * INV_T;
    float J = mt - logf(expf(mt) + S);
    float s = J;
#pragma unroll
    for (int o = 16; o > 0; o >>= 1) s += __shfl_xor_sync(0xffffffffu, s, o);
    if ((threadIdx.x & 31) == 0) red[threadIdx.x >> 5] = s;
    __syncthreads();
    if (threadIdx.x == 0) g_jpart[blockIdx.x] = red[0] + red[1] + red[2] + red[3];
}

__global__ void k_reduce(float* out) {
    __shared__ float red[8];
    int t = threadIdx.x; // 256
    float s = g_jpart[t];
#pragma unroll
    for (int o = 16; o > 0; o >>= 1) s += __shfl_xor_sync(0xffffffffu, s, o);
    if ((t & 31) == 0) red[t >> 5] = s;
    __syncthreads();
    if (t == 0) {
        float tot = 0.0f;
        for (int i = 0; i < 8; ++i) tot += red[i];
        out[0] = -tot / (float)BB;
    }
}

// ---------------------------------------------------------------------------
extern "C" void kernel_launch(void* const* d_in, const int* in_sizes, int n_in,
                              void* d_out, int out_size) {
    const float* feat = (const float*)d_in[0];
    const float* cent = (const float*)d_in[1];
    if (n_in >= 2 && in_sizes[0] == KK * DD && in_sizes[1] == BB * DD) {
        feat = (const float*)d_in[1];
        cent = (const float*)d_in[0];
    }

    cudaFuncSetAttribute((const void*)gemm_all,
                         cudaFuncAttributeMaxDynamicSharedMemorySize, SMEM_TOTAL);

    k_prep_feat<<<3072, 256>>>(feat);
    k_prep_cent<<<KK, 128>>>(cent);
    gemm_all<<<152, 256, SMEM_TOTAL>>>();
    k_sumS<<<KK / 256, 256>>>();
    k_finalj<<<JBLOCKS, 128>>>();
    k_reduce<<<1, 256>>>((float*)d_out);
}

// round 17
// speedup vs baseline: 1.0791x; 1.0082x over previous
#include <cuda_runtime.h>
#include <cuda_bf16.h>
#include <cstdint>
#include <math.h>

// Problem constants
#define BB 32768
#define KK 8192
#define DD 384
#define JBLOCKS 256

constexpr float INV_T = 1.0f / 0.07f;

// Tiling: CTA tile 128x256, k-chunk 128; 8 warps as 2(M) x 4(N), warp tile 64x64
#define BM 128
#define BN 256
#define BKC 128
constexpr int A_UNITS = DD / 8;              // 48 16B-units per A row
constexpr int A_SEC_BYTES = BM * 16 * 16;    // 32768 per kc-section
constexpr int A_BYTES = 3 * A_SEC_BYTES;     // 98304 per stripe
constexpr int B_CHUNK = BN * BKC * 2;        // 65536 per chunk
constexpr int CTRL    = A_BYTES + 2 * B_CHUNK;  // 229376
constexpr int SMEM_TOTAL = CTRL + 128;          // 229504

// Work units: 4 n-tiles (1024 cols) of one 128-row stripe = 12 chunks.
//   u < 2048         : GEMM1 (feat x cent): stripe=u>>3, seg=u&7
//   2048 <= u < 2336 : GEMM2 (cent x cent), TRIANGLE ONLY (seg >= floor(I/8)).
//     col-sums always -> g_centcol[I][.]; row-sums only when seg > floor(I/8).
#define NTILES 4
#define NCHUNK 12
#define G1UNITS 2048
#define G2UNITS 288
#define NUNITS  (G1UNITS + G2UNITS)
#define OSEG    32

// Pre-swizzled GMEM images + outputs (device globals: no allocation allowed)
// A images are SECTION-MAJOR: unit index = sec*2048 + r*16 + ((u&15)^(r&7)).
__device__ uint4 g_featS[BB * DD * 2 / 16];
__device__ uint4 g_centA[KK * DD * 2 / 16];
__device__ uint4 g_centB[KK * DD * 2 / 16];
__device__ float2 g_rowcand[(size_t)OSEG * BB]; // (max, argmax-bits) packed
__device__ float g_centpart[(size_t)OSEG * KK];  // row-sum partials (pre-zeroed)
__device__ float g_centcol[(size_t)64 * KK];     // col-sum partials (pre-zeroed)
__device__ float g_S[KK];                        // folded centroid sums
__device__ float g_jpart[JBLOCKS];
__device__ unsigned g_work;

// ---------------------------------------------------------------------------
__device__ __forceinline__ uint32_t smem_u32(const void* p) {
    return (uint32_t)__cvta_generic_to_shared(p);
}
__device__ __forceinline__ void mbar_init(uint32_t a, uint32_t c) {
    asm volatile("mbarrier.init.shared.b64 [%0], %1;" :: "r"(a), "r"(c) : "memory");
}
__device__ __forceinline__ void mbar_expect(uint32_t a, uint32_t bytes) {
    asm volatile("mbarrier.arrive.expect_tx.shared.b64 _, [%0], %1;"
                 :: "r"(a), "r"(bytes) : "memory");
}
__device__ __forceinline__ void bulk_g2s(uint32_t dst, const void* src,
                                         uint32_t bytes, uint32_t mb) {
    asm volatile(
        "cp.async.bulk.shared::cluster.global.mbarrier::complete_tx::bytes "
        "[%0], [%1], %2, [%3];"
        :: "r"(dst), "l"(src), "r"(bytes), "r"(mb) : "memory");
}
__device__ __forceinline__ void mbar_wait(uint32_t addr, uint32_t parity) {
    asm volatile(
        "{\n\t.reg .pred P;\n\t"
        "WL%=:\n\t"
        "mbarrier.try_wait.parity.acquire.cta.shared::cta.b64 P, [%0], %1, 0x989680;\n\t"
        "@P bra WD%=;\n\t"
        "bra WL%=;\n\t"
        "WD%=:\n\t}"
        :: "r"(addr), "r"(parity) : "memory");
}
__device__ __forceinline__ uint32_t atom_inc_acqrel(uint32_t addr) {
    uint32_t old;
    asm volatile("atom.add.acq_rel.cta.shared::cta.u32 %0, [%1], 1;"
                 : "=r"(old) : "r"(addr) : "memory");
    return old;
}
#define FENCE_ASYNC() asm volatile("fence.proxy.async.shared::cta;" ::: "memory")

__device__ __forceinline__ void ldsm4(uint32_t (&d)[4], uint32_t addr) {
    asm volatile("ldmatrix.sync.aligned.m8n8.x4.shared.b16 {%0,%1,%2,%3}, [%4];"
                 : "=r"(d[0]), "=r"(d[1]), "=r"(d[2]), "=r"(d[3]) : "r"(addr));
}

// Decode unit id -> (isG1, stripe, seg)
__device__ __forceinline__ void decode_unit(unsigned u, int& isG1,
                                            int& stripe, int& seg) {
    if (u < G1UNITS) {
        isG1 = 1; stripe = (int)u >> 3; seg = (int)u & 7;
    } else {
        isG1 = 0;
        int v = (int)u - G1UNITS, q = 0;
        while (v >= 8 * (8 - q)) { v -= 8 * (8 - q); ++q; }
        stripe = 8 * q + v / (8 - q);
        seg = q + v % (8 - q);
    }
}

// One ks step: 8 ldmatrix + 32 mma. ZC=true: first step of a tile, C=0.
template <bool ZC>
__device__ __forceinline__ void ks_step(int ks, uint32_t abase, uint32_t bbase,
                                        int wm, int wn, int lane,
                                        float (&acc)[4][8][4]) {
    uint32_t a[4][4], b[4][4];
#pragma unroll
    for (int mf = 0; mf < 4; ++mf) {
        int r = wm * 64 + mf * 16 + (lane & 15);
        int ul = ks * 2 + (lane >> 4);
        ldsm4(a[mf], abase + (uint32_t)(r * 16 + (ul ^ (r & 7))) * 16u);
    }
#pragma unroll
    for (int np = 0; np < 4; ++np) {
        int r = wn * 64 + np * 16 + (lane & 7) + ((lane >> 4) << 3);
        int uu = ks * 2 + ((lane >> 3) & 1);
        ldsm4(b[np], bbase + (uint32_t)(r * 16 + (uu ^ (r & 7))) * 16u);
    }
#pragma unroll
    for (int mf = 0; mf < 4; ++mf)
#pragma unroll
        for (int nf = 0; nf < 8; ++nf) {
            int np = nf >> 1, h = nf & 1;
            if (ZC) {
                asm volatile(
                    "mma.sync.aligned.m16n8k16.row.col.f32.bf16.bf16.f32 "
                    "{%0,%1,%2,%3}, {%4,%5,%6,%7}, {%8,%9}, {%10,%11,%12,%13};\n"
                    : "=f"(acc[mf][nf][0]), "=f"(acc[mf][nf][1]),
                      "=f"(acc[mf][nf][2]), "=f"(acc[mf][nf][3])
                    : "r"(a[mf][0]), "r"(a[mf][1]), "r"(a[mf][2]), "r"(a[mf][3]),
                      "r"(b[np][h * 2]), "r"(b[np][h * 2 + 1]),
                      "f"(0.0f), "f"(0.0f), "f"(0.0f), "f"(0.0f));
            } else {
                asm volatile(
                    "mma.sync.aligned.m16n8k16.row.col.f32.bf16.bf16.f32 "
                    "{%0,%1,%2,%3}, {%4,%5,%6,%7}, {%8,%9}, {%0,%1,%2,%3};\n"
                    : "+f"(acc[mf][nf][0]), "+f"(acc[mf][nf][1]),
                      "+f"(acc[mf][nf][2]), "+f"(acc[mf][nf][3])
                    : "r"(a[mf][0]), "r"(a[mf][1]), "r"(a[mf][2]), "r"(a[mf][3]),
                      "r"(b[np][h * 2]), "r"(b[np][h * 2 + 1]));
            }
        }
}

// ---------------------------------------------------------------------------
// Prep: features fp32 -> bf16 section-major stripes. Zeros outputs + g_work.
// ---------------------------------------------------------------------------
__global__ void k_prep_feat(const float* __restrict__ feat) {
    if (blockIdx.x == 0 && threadIdx.x == 0) g_work = 0u;
    const int gstride = gridDim.x * blockDim.x;
    const int gid = blockIdx.x * blockDim.x + threadIdx.x;
    for (int i = gid; i < OSEG * KK; i += gstride) g_centpart[i] = 0.0f;
    for (int i = gid; i < 64 * KK; i += gstride) g_centcol[i] = 0.0f;
    const int NU = BB * A_UNITS;
    for (int idx = gid; idx < NU; idx += gstride) {
        int u = idx % A_UNITS;
        int r = (idx / A_UNITS) % BM;
        int s = idx / (A_UNITS * BM);
        const float4* src =
            (const float4*)(feat + (size_t)(s * BM + r) * DD + u * 8);
        float4 f0 = src[0], f1 = src[1];
        __nv_bfloat162 p0 = __floats2bfloat162_rn(f0.x, f0.y);
        __nv_bfloat162 p1 = __floats2bfloat162_rn(f0.z, f0.w);
        __nv_bfloat162 p2 = __floats2bfloat162_rn(f1.x, f1.y);
        __nv_bfloat162 p3 = __floats2bfloat162_rn(f1.z, f1.w);
        uint4 v;
        v.x = *(uint32_t*)&p0; v.y = *(uint32_t*)&p1;
        v.z = *(uint32_t*)&p2; v.w = *(uint32_t*)&p3;
        g_featS[s * (BM * A_UNITS) + (u >> 4) * (BM * 16)
                + r * 16 + ((u & 15) ^ (r & 7))] = v;
    }
}

// ---------------------------------------------------------------------------
// Prep: centroids normalize -> bf16 as section-major A stripes + B chunks.
// ---------------------------------------------------------------------------
__global__ void k_prep_cent(const float* __restrict__ cent) {
    __shared__ float red[4];
    int row = blockIdx.x, t = threadIdx.x;
    const float* src = cent + (size_t)row * DD;
    float v0 = src[t], v1 = src[t + 128], v2 = src[t + 256];
    float s = v0 * v0 + v1 * v1 + v2 * v2;
#pragma unroll
    for (int o = 16; o > 0; o >>= 1) s += __shfl_xor_sync(0xffffffffu, s, o);
    if ((t & 31) == 0) red[t >> 5] = s;
    __syncthreads();
    float inv = 1.0f / fmaxf(sqrtf(red[0] + red[1] + red[2] + red[3]), 1e-12f);

    int j = -1;
    if (t < 48) j = t;
    else if (t >= 64 && t < 112) j = t - 64;
    if (j >= 0) {
        const float4* sp = (const float4*)(src + j * 8);
        float4 f0 = sp[0], f1 = sp[1];
        __nv_bfloat162 p0 = __floats2bfloat162_rn(f0.x * inv, f0.y * inv);
        __nv_bfloat162 p1 = __floats2bfloat162_rn(f0.z * inv, f0.w * inv);
        __nv_bfloat162 p2 = __floats2bfloat162_rn(f1.x * inv, f1.y * inv);
        __nv_bfloat162 p3 = __floats2bfloat162_rn(f1.z * inv, f1.w * inv);
        uint4 v;
        v.x = *(uint32_t*)&p0; v.y = *(uint32_t*)&p1;
        v.z = *(uint32_t*)&p2; v.w = *(uint32_t*)&p3;
        if (t < 48) {
            int sA = row >> 7, r = row & 127;
            g_centA[sA * (BM * A_UNITS) + (j >> 4) * (BM * 16)
                    + r * 16 + ((j & 15) ^ (r & 7))] = v;
        } else {
            int nt = row >> 8, rr = row & 255, kc = j >> 4, uu = j & 15;
            g_centB[(size_t)(nt * 3 + kc) * 4096 + rr * 16 + (uu ^ (rr & 7))] = v;
        }
    }
}

// ---------------------------------------------------------------------------
// Persistent fused GEMM (152 CTAs, never-drain pipeline). GEMM2 = upper
// triangle only; epilogue emits row sums AND exact 128-row column sums.
// ---------------------------------------------------------------------------
__global__ void __launch_bounds__(256, 1) gemm_all() {
    extern __shared__ char smem[];
    const int tid = threadIdx.x, lane = tid & 31, wid = tid >> 5;
    const int wm = wid >> 2, wn = wid & 3;
    const uint32_t sb = smem_u32(smem);
    const uint32_t mbA = sb + CTRL;          // A section mbars[3]
    const uint32_t mbF = sb + CTRL + 24;     // B full mbars[2]
    const uint32_t cnt = sb + CTRL + 40;     // 12 monotonic u32 counters
    uint32_t* const u_slot = (uint32_t*)(smem + CTRL + 88);

    auto issueA = [&](unsigned uu, int sec) {
        int g1, stripe, seg;
        decode_unit(uu, g1, stripe, seg);
        const uint4* src = (g1 ? g_featS : g_centA)
                         + (size_t)stripe * (BM * A_UNITS) + sec * (BM * 16);
        mbar_expect(mbA + sec * 8, A_SEC_BYTES);
        bulk_g2s(sb + sec * A_SEC_BYTES, src, A_SEC_BYTES, mbA + sec * 8);
    };
    auto issueB = [&](unsigned uu, int c) {
        int g1, stripe, seg;
        decode_unit(uu, g1, stripe, seg);
        const uint4* src =
            g_centB + (size_t)((seg * NTILES + c / 3) * 3 + c % 3) * 4096;
        int slot = c & 1;
        mbar_expect(mbF + slot * 8, B_CHUNK);
        bulk_g2s(sb + A_BYTES + slot * B_CHUNK, src, B_CHUNK, mbF + slot * 8);
    };

    if (tid == 0) {
        mbar_init(mbA, 1); mbar_init(mbA + 8, 1); mbar_init(mbA + 16, 1);
        mbar_init(mbF, 1); mbar_init(mbF + 8, 1);
        *u_slot = atomicAdd(&g_work, 1u);
    }
    if (tid < NCHUNK) *(uint32_t*)(smem + CTRL + 40 + tid * 4) = 0u;
    __syncthreads();

    unsigned u = *u_slot;
    int k = 0;
    if (tid == 0 && u < NUNITS) {
        issueA(u, 0); issueA(u, 1); issueA(u, 2);
        issueB(u, 0); issueB(u, 1);
    }

    while (u < NUNITS) {
        int isG1, stripe, seg;
        decode_unit(u, isG1, stripe, seg);
        const int row0 = stripe * BM;
        const int col_begin = seg * (NTILES * BN);

        float acc[4][8][4];
        float bestv[8];
        int   besti[8];
        float rsum[8];
#pragma unroll
        for (int s = 0; s < 8; ++s) {
            bestv[s] = __int_as_float(0xff800000);
            besti[s] = 0x7fffffff;
            rsum[s]  = 0.0f;
        }

        for (int c = 0; c < NCHUNK; ++c) {
            const int slot = c & 1, kc = c % 3, nt = c / 3;
            if (c < 3) mbar_wait(mbA + c * 8, (uint32_t)(k & 1));
            mbar_wait(mbF + slot * 8, (uint32_t)((c >> 1) & 1));
            const uint32_t bbase = sb + A_BYTES + slot * B_CHUNK;
            const uint32_t abase = sb + kc * A_SEC_BYTES;

            if (kc == 0) {
                ks_step<true>(0, abase, bbase, wm, wn, lane, acc);
#pragma unroll
                for (int ks = 1; ks < 8; ++ks)
                    ks_step<false>(ks, abase, bbase, wm, wn, lane, acc);
            } else {
#pragma unroll
                for (int ks = 0; ks < 8; ++ks)
                    ks_step<false>(ks, abase, bbase, wm, wn, lane, acc);
            }

            // Buffer release + refill/prefetch by the LAST finisher of chunk c.
            if (lane == 0) {
                uint32_t old = atom_inc_acqrel(cnt + c * 4);
                if (old == (uint32_t)(8 * k + 7)) {
                    FENCE_ASYNC();
                    if (c <= NCHUNK - 3) issueB(u, c + 2);
                    if (c == 8) {
                        *u_slot = atomicAdd(&g_work, 1u);   // grab next unit
                    } else if (c == 9) {
                        unsigned un = *u_slot;
                        if (un < NUNITS) issueA(un, 0);
                    } else if (c == 10) {
                        unsigned un = *u_slot;
                        if (un < NUNITS) { issueA(un, 1); issueB(un, 0); }
                    } else if (c == 11) {
                        unsigned un = *u_slot;
                        if (un < NUNITS) { issueA(un, 2); issueB(un, 1); }
                    }
                }
            }

            if (kc == 2) {
                int cbase = col_begin + nt * BN + wn * 64 + 2 * (lane & 3);
                if (isG1) {
#pragma unroll
                    for (int mf = 0; mf < 4; ++mf)
#pragma unroll
                        for (int nf = 0; nf < 8; ++nf) {
                            int col = cbase + nf * 8;
                            int s0 = mf * 2, s1 = mf * 2 + 1;
                            float v0 = acc[mf][nf][0], v1 = acc[mf][nf][1];
                            float v2 = acc[mf][nf][2], v3 = acc[mf][nf][3];
                            if (v0 > bestv[s0]) { bestv[s0] = v0; besti[s0] = col; }
                            if (v1 > bestv[s0]) { bestv[s0] = v1; besti[s0] = col + 1; }
                            if (v2 > bestv[s1]) { bestv[s1] = v2; besti[s1] = col; }
                            if (v3 > bestv[s1]) { bestv[s1] = v3; besti[s1] = col + 1; }
                        }
                } else {
                    // Row sums AND 128-row column sums for this 128x256 tile.
                    float csum[16];
#pragma unroll
                    for (int jj = 0; jj < 16; ++jj) csum[jj] = 0.0f;
#pragma unroll
                    for (int mf = 0; mf < 4; ++mf)
#pragma unroll
                        for (int nf = 0; nf < 8; ++nf) {
                            int s0 = mf * 2, s1 = mf * 2 + 1;
                            float e0 = __expf(acc[mf][nf][0] * INV_T);
                            float e1 = __expf(acc[mf][nf][1] * INV_T);
                            float e2 = __expf(acc[mf][nf][2] * INV_T);
                            float e3 = __expf(acc[mf][nf][3] * INV_T);
                            rsum[s0] += e0 + e1;
                            rsum[s1] += e2 + e3;
                            csum[nf * 2]     += e0 + e2;
                            csum[nf * 2 + 1] += e1 + e3;
                        }
#pragma unroll
                    for (int jj = 0; jj < 16; ++jj) {
                        float v = csum[jj];
                        v += __shfl_xor_sync(0xffffffffu, v, 4);
                        v += __shfl_xor_sync(0xffffffffu, v, 8);
                        v += __shfl_xor_sync(0xffffffffu, v, 16);
                        if (lane < 4) {
                            int col = cbase + (jj >> 1) * 8 + (jj & 1);
                            // exactly 2 adders per slot (wm=0, wm=1): a+b is
                            // order-independent -> deterministic
                            atomicAdd(&g_centcol[(size_t)stripe * KK + col], v);
                        }
                    }
                }
            }
        }

        // Direct-to-global writeback (overlaps next unit's prefetch fills).
        const int oseg = seg * 4 + wn;
#pragma unroll
        for (int s = 0; s < 8; ++s) {
            int row = wm * 64 + (s >> 1) * 16 + (lane >> 2) + (s & 1) * 8;
            if (isG1) {
                float vv = bestv[s];
                int ii = besti[s];
#pragma unroll
                for (int o = 1; o <= 2; o <<= 1) {
                    float ov = __shfl_xor_sync(0xffffffffu, vv, o);
                    int oi = __shfl_xor_sync(0xffffffffu, ii, o);
                    if (ov > vv || (ov == vv && oi < ii)) { vv = ov; ii = oi; }
                }
                if ((lane & 3) == 0) {
                    float2 cand;
                    cand.x = vv;
                    cand.y = __int_as_float(ii);
                    g_rowcand[(size_t)oseg * BB + row0 + row] = cand;
                }
            } else if (seg > (stripe >> 3)) {   // diagonal units: row sums unused
                float vv = rsum[s];
                vv += __shfl_xor_sync(0xffffffffu, vv, 1);
                vv += __shfl_xor_sync(0xffffffffu, vv, 2);
                if ((lane & 3) == 0)
                    g_centpart[(size_t)oseg * KK + row0 + row] = vv;
            }
        }

        __syncthreads();   // broadcast u_slot; all warps aligned to next unit
        ++k;
        u = *u_slot;
    }
}

// ---------------------------------------------------------------------------
// Fold S[j]: 4 threads per j, 24 partials each (fixed o-ranges), combined in
// fixed order via smem -> deterministic. 128 CTAs -> latency well hidden.
// ---------------------------------------------------------------------------
__global__ void k_sumS() {
    __shared__ float part[4][64];
    const int jl = threadIdx.x & 63, oq = threadIdx.x >> 6;
    const int j = blockIdx.x * 64 + jl;
    float s = 0.0f;
#pragma unroll 4
    for (int o = oq * 24; o < oq * 24 + 24; ++o) {
        s += (o < OSEG) ? g_centpart[(size_t)o * KK + j]
                        : g_centcol[(size_t)(o - OSEG) * KK + j];
    }
    part[oq][jl] = s;
    __syncthreads();
    if (oq == 0)
        g_S[j] = ((part[0][jl] + part[1][jl]) + part[2][jl]) + part[3][jl];
}

// ---------------------------------------------------------------------------
// Per-sample loss: merge 32 packed candidates/row; single gather of S[a].
// ---------------------------------------------------------------------------
__global__ void k_finalj() {
    __shared__ float red[4];
    int i = blockIdx.x * 128 + threadIdx.x;
    float m = __int_as_float(0xff800000);
    int a = 0x7fffffff;
#pragma unroll 8
    for (int o = 0; o < OSEG; ++o) {
        float2 cand = g_rowcand[(size_t)o * BB + i];
        float ms = cand.x;
        int as_ = __float_as_int(cand.y);
        if (ms > m || (ms == m && as_ < a)) { m = ms; a = as_; }
    }
    float S = g_S[a];
    float mt = m * INV_T;
    float J = mt - logf(expf(mt) + S);
    float s = J;
#pragma unroll
    for (int o = 16; o > 0; o >>= 1) s += __shfl_xor_sync(0xffffffffu, s, o);
    if ((threadIdx.x & 31) == 0) red[threadIdx.x >> 5] = s;
    __syncthreads();
    if (threadIdx.x == 0) g_jpart[blockIdx.x] = red[0] + red[1] + red[2] + red[3];
}

__global__ void k_reduce(float* out) {
    __shared__ float red[8];
    int t = threadIdx.x; // 256
    float s = g_jpart[t];
#pragma unroll
    for (int o = 16; o > 0; o >>= 1) s += __shfl_xor_sync(0xffffffffu, s, o);
    if ((t & 31) == 0) red[t >> 5] = s;
    __syncthreads();
    if (t == 0) {
        float tot = 0.0f;
        for (int i = 0; i < 8; ++i) tot += red[i];
        out[0] = -tot / (float)BB;
    }
}

// ---------------------------------------------------------------------------
extern "C" void kernel_launch(void* const* d_in, const int* in_sizes, int n_in,
                              void* d_out, int out_size) {
    const float* feat = (const float*)d_in[0];
    const float* cent = (const float*)d_in[1];
    if (n_in >= 2 && in_sizes[0] == KK * DD && in_sizes[1] == BB * DD) {
        feat = (const float*)d_in[1];
        cent = (const float*)d_in[0];
    }

    cudaFuncSetAttribute((const void*)gemm_all,
                         cudaFuncAttributeMaxDynamicSharedMemorySize, SMEM_TOTAL);

    k_prep_feat<<<3072, 256>>>(feat);
    k_prep_cent<<<KK, 128>>>(cent);
    gemm_all<<<152, 256, SMEM_TOTAL>>>();
    k_sumS<<<KK / 64, 256>>>();
    k_finalj<<<JBLOCKS, 128>>>();
    k_reduce<<<1, 256>>>((float*)d_out);
}